// round 14
// baseline (speedup 1.0000x reference)
#include <cuda_runtime.h>
#include <cuda_bf16.h>
#include <cuda_fp16.h>
#include <cstdint>
#include <math.h>

#define B_  4
#define N_  576
#define T_  3
#define C_  768
#define H_  12
#define P_  9
#define DH_ 64
#define HP_ 24
#define SCALE_ 0.125f
#define BN_ (B_ * N_)
#define CKV_ (2 * C_)       // 1536
#define MKV_ (BN_ * T_)     // 6912
#define NOFF_ (H_ * P_ * 2) // 216
#define NQOFF_ 1024         // 768 (q) + 256 (off padded)

typedef unsigned long long u64;

// ---------------- scratch (device globals) -----------------------------------
__device__ __half g_xh[MKV_ * C_];        // x in fp16
__device__ __half g_wkvT[CKV_ * C_];      // [n][k]; n<768: Wk, else Wv (fp16)
__device__ __nv_bfloat16 g_qbf_hi[BN_ * C_];
__device__ __nv_bfloat16 g_qbf_lo[BN_ * C_];
__device__ __nv_bfloat16 g_wqoffT_hi[NQOFF_ * C_];
__device__ __nv_bfloat16 g_wqoffT_lo[NQOFF_ * C_];
__device__ __nv_bfloat16 g_wprojT_hi[C_ * C_];
__device__ __nv_bfloat16 g_wprojT_lo[C_ * C_];
__device__ __nv_bfloat16 g_ahi[BN_ * C_];
__device__ __nv_bfloat16 g_alo[BN_ * C_];
__device__ float g_bias_qoff[NQOFF_];

__device__ float g_kv[MKV_ * CKV_];      // fp32 KV (no cvt in attn)
__device__ float g_qoff[BN_ * NQOFF_];

// ---------------- PTX helpers ---------------------------------------------------
__device__ __forceinline__ uint32_t smem_to_u32(const void* p) {
    uint32_t a;
    asm("{ .reg .u64 t; cvta.to.shared.u64 t, %1; cvt.u32.u64 %0, t; }"
        : "=r"(a) : "l"(p));
    return a;
}
__device__ __forceinline__ void cp16(uint32_t dst, const void* src) {
    asm volatile("cp.async.cg.shared.global [%0], [%1], 16;"
                 :: "r"(dst), "l"(src));
}
#define CP_COMMIT() asm volatile("cp.async.commit_group;" ::: "memory")
#define CP_WAIT0()  asm volatile("cp.async.wait_group 0;" ::: "memory")
#define CP_WAIT1()  asm volatile("cp.async.wait_group 1;" ::: "memory")
#define CP_WAIT2()  asm volatile("cp.async.wait_group 2;" ::: "memory")

__device__ __forceinline__ void ldm4(uint32_t* r, uint32_t addr) {
    asm volatile("ldmatrix.sync.aligned.m8n8.x4.shared.b16 {%0,%1,%2,%3}, [%4];"
                 : "=r"(r[0]), "=r"(r[1]), "=r"(r[2]), "=r"(r[3]) : "r"(addr));
}
__device__ __forceinline__ void mma_bf16(float* c, const uint32_t* a,
                                         uint32_t b0, uint32_t b1) {
    asm volatile(
        "mma.sync.aligned.m16n8k16.row.col.f32.bf16.bf16.f32 "
        "{%0,%1,%2,%3}, {%4,%5,%6,%7}, {%8,%9}, {%0,%1,%2,%3};"
        : "+f"(c[0]), "+f"(c[1]), "+f"(c[2]), "+f"(c[3])
        : "r"(a[0]), "r"(a[1]), "r"(a[2]), "r"(a[3]), "r"(b0), "r"(b1));
}
__device__ __forceinline__ void mma_fp16(float* c, const uint32_t* a,
                                         uint32_t b0, uint32_t b1) {
    asm volatile(
        "mma.sync.aligned.m16n8k16.row.col.f32.f16.f16.f32 "
        "{%0,%1,%2,%3}, {%4,%5,%6,%7}, {%8,%9}, {%0,%1,%2,%3};"
        : "+f"(c[0]), "+f"(c[1]), "+f"(c[2]), "+f"(c[3])
        : "r"(a[0]), "r"(a[1]), "r"(a[2]), "r"(a[3]), "r"(b0), "r"(b1));
}

// packed f32x2 math
__device__ __forceinline__ void fma2p(u64& d, u64 a, u64 b) {
    asm("fma.rn.f32x2 %0, %1, %2, %0;" : "+l"(d) : "l"(a), "l"(b));
}
__device__ __forceinline__ u64 mul2p(u64 a, u64 b) {
    u64 d; asm("mul.rn.f32x2 %0, %1, %2;" : "=l"(d) : "l"(a), "l"(b)); return d;
}
__device__ __forceinline__ u64 pack2p(float lo, float hi) {
    u64 d; asm("mov.b64 %0, {%1, %2};" : "=l"(d) : "f"(lo), "f"(hi)); return d;
}
__device__ __forceinline__ float2 unpack2p(u64 v) {
    float2 f; asm("mov.b64 {%0, %1}, %2;" : "=f"(f.x), "=f"(f.y) : "l"(v)); return f;
}

// ---------------- prep kernels ---------------------------------------------------
__device__ __forceinline__ void split_bf(float v, __nv_bfloat16& hi, __nv_bfloat16& lo) {
    hi = __float2bfloat16(v);
    lo = __float2bfloat16(v - __bfloat162float(hi));
}

__global__ void conv_x_kernel(const float* __restrict__ x) {
    int idx = blockIdx.x * blockDim.x + threadIdx.x;  // over MKV_*C_/4
    if (idx >= MKV_ * C_ / 4) return;
    float4 v = ((const float4*)x)[idx];
    ((__half2*)g_xh)[idx * 2]     = __floats2half2_rn(v.x, v.y);
    ((__half2*)g_xh)[idx * 2 + 1] = __floats2half2_rn(v.z, v.w);

    int token = idx / (C_ / 4);
    if (token % T_ == 1) {
        int bn = token / T_;
        int c4 = idx % (C_ / 4);
        int qidx = bn * (C_ / 4) + c4;
        __nv_bfloat16 h0, l0, h1, l1, h2, l2, h3, l3;
        split_bf(v.x, h0, l0); split_bf(v.y, h1, l1);
        split_bf(v.z, h2, l2); split_bf(v.w, h3, l3);
        ((__nv_bfloat162*)g_qbf_hi)[qidx * 2]     = __nv_bfloat162(h0, h1);
        ((__nv_bfloat162*)g_qbf_hi)[qidx * 2 + 1] = __nv_bfloat162(h2, h3);
        ((__nv_bfloat162*)g_qbf_lo)[qidx * 2]     = __nv_bfloat162(l0, l1);
        ((__nv_bfloat162*)g_qbf_lo)[qidx * 2 + 1] = __nv_bfloat162(l2, l3);
    }
}

__global__ void tpose_split_all_kernel(
    const float* __restrict__ Wq, const float* __restrict__ Wk,
    const float* __restrict__ Wv, const float* __restrict__ Wproj,
    const float* __restrict__ Woff, const float* __restrict__ boff)
{
    if (blockIdx.z == 0 && blockIdx.x == 0 && blockIdx.y == 0) {
        int t = threadIdx.y * 32 + threadIdx.x;
        for (int i = t; i < NQOFF_; i += 256)
            g_bias_qoff[i] = (i >= 768 && i < 768 + NOFF_) ? boff[i - 768] : 0.f;
    }

    const float* src;
    __half* dh = nullptr;
    __nv_bfloat16 *dhi = nullptr, *dlo = nullptr;
    int N, dstRows;
    switch (blockIdx.z) {
        case 0: src = Wq;    dhi = g_wqoffT_hi; dlo = g_wqoffT_lo; N = C_; dstRows = C_; break;
        case 1: src = Wk;    dh = g_wkvT;                 N = C_;   dstRows = C_;  break;
        case 2: src = Wv;    dh = g_wkvT + (long)C_ * C_; N = C_;   dstRows = C_;  break;
        case 3: src = Wproj; dhi = g_wprojT_hi; dlo = g_wprojT_lo; N = C_; dstRows = C_; break;
        default: src = Woff; dhi = g_wqoffT_hi + (long)768 * C_;
                             dlo = g_wqoffT_lo + (long)768 * C_;   N = NOFF_; dstRows = 256; break;
    }
    int n0 = blockIdx.x * 32, k0 = blockIdx.y * 32;
    if (n0 >= dstRows) return;

    __shared__ float tile[32][33];
    int tx = threadIdx.x, ty = threadIdx.y;
#pragma unroll
    for (int j = 0; j < 4; j++) {
        int k = k0 + ty + j * 8, n = n0 + tx;
        tile[ty + j * 8][tx] = (n < N) ? src[(long)k * N + n] : 0.f;
    }
    __syncthreads();
#pragma unroll
    for (int j = 0; j < 4; j++) {
        int n = n0 + ty + j * 8, k = k0 + tx;
        if (n < dstRows) {
            float v = tile[tx][ty + j * 8];
            if (dh) {
                dh[(long)n * C_ + k] = __float2half_rn(v);
            } else {
                __nv_bfloat16 hi, lo;
                split_bf(v, hi, lo);
                dhi[(long)n * C_ + k] = hi;
                dlo[(long)n * C_ + k] = lo;
            }
        }
    }
}

// ---------------- merged GEMM kernel: 256 threads, 2 CTAs/SM ---------------------
#define FTILE 16384
#define FSTAGE (2 * FTILE)
#define MSMEM  (3 * FSTAGE)   // 98304

__device__ __forceinline__ void gemm_fp16_body256(
    const __half* __restrict__ Ah, long lda,
    const __half* __restrict__ Bh,
    float* __restrict__ C, int ldc, int K,
    int row0, int col0, char* smem)
{
    uint32_t sb = smem_to_u32(smem);
    int tid = threadIdx.x;
    int wid = tid >> 5, lane = tid & 31;
    int warp_m = wid & 3;
    int warp_n = wid >> 2;
    const int NKITER = K / 64;

    int rr[4], cc[4], doff[4];
#pragma unroll
    for (int j = 0; j < 4; j++) {
        int u = tid + j * 256;
        int r = u >> 3, cu = u & 7;
        rr[j] = r; cc[j] = cu;
        doff[j] = ((r << 3) + (cu ^ (r & 7))) << 4;
    }

    const __half* gp[2] = {Ah, Bh};
    long  st[2] = {lda, (long)K};
    int   rb[2] = {row0, col0};

#pragma unroll
    for (int s = 0; s < 2; s++) {
        uint32_t sstage = sb + s * FSTAGE;
        int k0 = s * 64;
#pragma unroll
        for (int a = 0; a < 2; a++) {
            uint32_t sdst = sstage + a * FTILE;
            const __half* g = gp[a];
#pragma unroll
            for (int j = 0; j < 4; j++)
                cp16(sdst + doff[j],
                     g + (long)(rb[a] + rr[j]) * st[a] + k0 + cc[j] * 8);
        }
        CP_COMMIT();
    }

    float acc[2][8][4];
#pragma unroll
    for (int mf = 0; mf < 2; mf++)
#pragma unroll
        for (int nf = 0; nf < 8; nf++)
#pragma unroll
            for (int e = 0; e < 4; e++) acc[mf][nf][e] = 0.f;

    int a_r = warp_m * 32 + (lane & 7) + ((lane & 8) ? 8 : 0);
    int a_usel = (lane & 16) ? 1 : 0;
    int b_rbase = warp_n * 64 + (lane & 7) + ((lane & 16) ? 8 : 0);
    int b_usel = (lane & 8) ? 1 : 0;

    int bufc = 0, bufn = 2;
    for (int kc = 0; kc < NKITER; kc++) {
        if (kc + 2 < NKITER) {
            uint32_t sstage = sb + bufn * FSTAGE;
            int k0 = (kc + 2) * 64;
#pragma unroll
            for (int a = 0; a < 2; a++) {
                uint32_t sdst = sstage + a * FTILE;
                const __half* g = gp[a];
#pragma unroll
                for (int j = 0; j < 4; j++)
                    cp16(sdst + doff[j],
                         g + (long)(rb[a] + rr[j]) * st[a] + k0 + cc[j] * 8);
            }
            CP_COMMIT();
            CP_WAIT2();
        } else if (kc + 1 < NKITER) {
            CP_WAIT1();
        } else {
            CP_WAIT0();
        }
        __syncthreads();

        uint32_t s = sb + bufc * FSTAGE;
        uint32_t sA = s, sB = s + FTILE;

#pragma unroll
        for (int ks = 0; ks < 4; ks++) {
            uint32_t af[2][4];
#pragma unroll
            for (int mf = 0; mf < 2; mf++) {
                int r = a_r + mf * 16;
                int u = ks * 2 + a_usel;
                uint32_t off = (uint32_t)(((r << 3) + (u ^ (r & 7))) << 4);
                ldm4(af[mf], sA + off);
            }
#pragma unroll
            for (int np = 0; np < 4; np++) {
                uint32_t bf[4];
                int r = b_rbase + np * 16;
                int u = ks * 2 + b_usel;
                uint32_t off = (uint32_t)(((r << 3) + (u ^ (r & 7))) << 4);
                ldm4(bf, sB + off);
#pragma unroll
                for (int mf = 0; mf < 2; mf++)
#pragma unroll
                    for (int jj = 0; jj < 2; jj++)
                        mma_fp16(acc[mf][np * 2 + jj], af[mf],
                                 bf[jj * 2], bf[jj * 2 + 1]);
            }
        }
        __syncthreads();
        bufc = (bufc == 2) ? 0 : bufc + 1;
        bufn = (bufn == 2) ? 0 : bufn + 1;
    }

#pragma unroll
    for (int mf = 0; mf < 2; mf++) {
        int m = row0 + warp_m * 32 + mf * 16 + (lane >> 2);
#pragma unroll
        for (int nf = 0; nf < 8; nf++) {
            int n = col0 + warp_n * 64 + nf * 8 + (lane & 3) * 2;
            float2 v0 = make_float2(acc[mf][nf][0], acc[mf][nf][1]);
            float2 v1 = make_float2(acc[mf][nf][2], acc[mf][nf][3]);
            *(float2*)(C + (long)m * ldc + n)       = v0;
            *(float2*)(C + (long)(m + 8) * ldc + n) = v1;
        }
    }
}

#define QTILE 16384
__device__ __forceinline__ void gemm_bf16x3_body256(
    const __nv_bfloat16* __restrict__ Ahi,
    const __nv_bfloat16* __restrict__ Alo, long lda,
    const __nv_bfloat16* __restrict__ Bhi,
    const __nv_bfloat16* __restrict__ Blo,
    const float* __restrict__ bias,
    float* __restrict__ C, int ldc, int Nstore, int K,
    int row0, int col0, char* smem)
{
    uint32_t sb = smem_to_u32(smem);
    int tid = threadIdx.x;
    int wid = tid >> 5, lane = tid & 31;
    int warp_m = wid & 3;
    int warp_n = wid >> 2;
    const int NKITER = K / 64;

    int rr[4], cc[4], doff[4];
#pragma unroll
    for (int j = 0; j < 4; j++) {
        int u = tid + j * 256;
        int r = u >> 3, cu = u & 7;
        rr[j] = r; cc[j] = cu;
        doff[j] = ((r << 3) + (cu ^ (r & 7))) << 4;
    }

    const __nv_bfloat16* gp[4] = {Ahi, Alo, Bhi, Blo};
    long  st[4] = {lda, lda, (long)K, (long)K};
    int   rb[4] = {row0, row0, col0, col0};

    float acc[2][8][4];
#pragma unroll
    for (int mf = 0; mf < 2; mf++)
#pragma unroll
        for (int nf = 0; nf < 8; nf++)
#pragma unroll
            for (int e = 0; e < 4; e++) acc[mf][nf][e] = 0.f;

    int a_r = warp_m * 32 + (lane & 7) + ((lane & 8) ? 8 : 0);
    int a_usel = (lane & 16) ? 1 : 0;
    int b_rbase = warp_n * 64 + (lane & 7) + ((lane & 16) ? 8 : 0);
    int b_usel = (lane & 8) ? 1 : 0;

    for (int kc = 0; kc < NKITER; kc++) {
        int k0 = kc * 64;
#pragma unroll
        for (int a = 0; a < 4; a++) {
            uint32_t sdst = sb + a * QTILE;
            const __nv_bfloat16* g = gp[a];
#pragma unroll
            for (int j = 0; j < 4; j++)
                cp16(sdst + doff[j],
                     g + (long)(rb[a] + rr[j]) * st[a] + k0 + cc[j] * 8);
        }
        CP_COMMIT();
        CP_WAIT0();
        __syncthreads();

        uint32_t sAhi = sb, sAlo = sb + QTILE;
        uint32_t sBhi = sb + 2 * QTILE, sBlo = sb + 3 * QTILE;

#pragma unroll
        for (int ks = 0; ks < 4; ks++) {
            uint32_t ah[2][4], al[2][4];
#pragma unroll
            for (int mf = 0; mf < 2; mf++) {
                int r = a_r + mf * 16;
                int u = ks * 2 + a_usel;
                uint32_t off = (uint32_t)(((r << 3) + (u ^ (r & 7))) << 4);
                ldm4(ah[mf], sAhi + off);
                ldm4(al[mf], sAlo + off);
            }
#pragma unroll
            for (int np = 0; np < 4; np++) {
                uint32_t bh[4], bl[4];
                int r = b_rbase + np * 16;
                int u = ks * 2 + b_usel;
                uint32_t off = (uint32_t)(((r << 3) + (u ^ (r & 7))) << 4);
                ldm4(bh, sBhi + off);
                ldm4(bl, sBlo + off);
#pragma unroll
                for (int mf = 0; mf < 2; mf++)
#pragma unroll
                    for (int jj = 0; jj < 2; jj++) {
                        float* a4 = acc[mf][np * 2 + jj];
                        mma_bf16(a4, ah[mf], bh[jj * 2], bh[jj * 2 + 1]);
                        mma_bf16(a4, ah[mf], bl[jj * 2], bl[jj * 2 + 1]);
                        mma_bf16(a4, al[mf], bh[jj * 2], bh[jj * 2 + 1]);
                    }
            }
        }
        __syncthreads();
    }

#pragma unroll
    for (int mf = 0; mf < 2; mf++) {
        int m = row0 + warp_m * 32 + mf * 16 + (lane >> 2);
#pragma unroll
        for (int nf = 0; nf < 8; nf++) {
            int n = col0 + warp_n * 64 + nf * 8 + (lane & 3) * 2;
            if (n < Nstore) {
                float2 v0, v1;
                v0.x = acc[mf][nf][0]; v0.y = acc[mf][nf][1];
                v1.x = acc[mf][nf][2]; v1.y = acc[mf][nf][3];
                if (bias) {
                    float bx = bias[n], by = bias[n + 1];
                    v0.x += bx; v0.y += by;
                    v1.x += bx; v1.y += by;
                }
                *(float2*)(C + (long)m * ldc + n)       = v0;
                *(float2*)(C + (long)(m + 8) * ldc + n) = v1;
            }
        }
    }
}

#define QO_BLOCKS 144
__global__ __launch_bounds__(256, 2)
void gemm_merged_kernel()
{
    extern __shared__ char smem[];
    int bid = blockIdx.x;
    if (bid < QO_BLOCKS) {
        int bx = bid % 8, by = bid / 8;
        gemm_bf16x3_body256(g_qbf_hi, g_qbf_lo, C_,
                            g_wqoffT_hi, g_wqoffT_lo, g_bias_qoff,
                            g_qoff, NQOFF_, 768 + NOFF_, C_,
                            by * 128, bx * 128, smem);
    } else {
        int b2 = bid - QO_BLOCKS;
        int bx = b2 % 12, by = b2 / 12;
        gemm_fp16_body256(g_xh, C_, g_wkvT,
                          g_kv, CKV_, C_, by * 128, bx * 128, smem);
    }
}

__global__ __launch_bounds__(256, 2)
void gemm_proj_kernel(const float* __restrict__ bias, float* __restrict__ C)
{
    extern __shared__ char smem[];
    gemm_bf16x3_body256(g_ahi, g_alo, C_, g_wprojT_hi, g_wprojT_lo, bias,
                        C, C_, C_, C_, blockIdx.y * 128, blockIdx.x * 128, smem);
}

// ---------------- deformable attention core (packed f32x2) ------------------------
__global__ __launch_bounds__(384, 2) void attn_kernel(
    const float* __restrict__ mask,
    const float* __restrict__ suppress_p)
{
    int bn = blockIdx.x;
    int b  = bn / N_;
    int n  = bn % N_;
    int h    = threadIdx.x >> 5;
    int lane = threadIdx.x & 31;
    int part = lane >> 4;
    int ch   = (lane & 15) * 4;

    float suppress = *suppress_p;
    float mk  = mask[bn];
    float sw  = 1.f - suppress * mk;
    float moff = suppress * mk * 0.1f;

    float refx = (float)(n % HP_) * (2.f / 23.f) - 1.f;
    float refy = (float)(n / HP_) * (2.f / 23.f) - 1.f;

    const float* rowbase = g_qoff + bn * NQOFF_;
    ulonglong2 qq = *(const ulonglong2*)(rowbase + h * DH_ + ch);

    const float* offrow = rowbase + 768 + h * (P_ * 2);
    float offv = (lane < P_ * 2) ? offrow[lane] : 0.f;

    int base_part = h * DH_ + part * C_ + ch;
    int pixbase = b * N_;

    float m0 = -1e30f, m1 = -1e30f, m2 = -1e30f;
    float s0 = 0.f, s1 = 0.f, s2 = 0.f;
    u64 o0l = 0, o0h = 0, o1l = 0, o1h = 0, o2l = 0, o2h = 0;

#pragma unroll
    for (int p = 0; p < P_; p++) {
        float ox = __shfl_sync(0xffffffffu, offv, 2 * p)     - moff;
        float oy = __shfl_sync(0xffffffffu, offv, 2 * p + 1) - moff;
        float xs = (refx + ox + 1.f) * 11.5f;
        float ys = (refy + oy + 1.f) * 11.5f;
        float x0f = floorf(xs), y0f = floorf(ys);
        int   x0 = (int)x0f,  y0 = (int)y0f;
        float wx1 = xs - x0f, wy1 = ys - y0f;
        float wx0 = 1.f - wx1, wy0 = 1.f - wy1;

        u64 a0l = 0, a0h = 0, a1l = 0, a1h = 0, a2l = 0, a2h = 0;
#pragma unroll
        for (int c = 0; c < 4; c++) {
            int dx = c & 1, dy = c >> 1;
            int ix = x0 + dx, iy = y0 + dy;
            float valid = (ix >= 0 && ix < HP_ && iy >= 0 && iy < HP_) ? 1.f : 0.f;
            float w = (dx ? wx1 : wx0) * (dy ? wy1 : wy0) * valid;
            u64 ww = pack2p(w, w);
            int ixc = min(max(ix, 0), HP_ - 1);
            int iyc = min(max(iy, 0), HP_ - 1);
            int idx = (pixbase + iyc * HP_ + ixc) * (T_ * CKV_) + base_part;
            const float* kvp = g_kv + idx;
            ulonglong2 kv0 = *(const ulonglong2*)(kvp);
            ulonglong2 kv1 = *(const ulonglong2*)(kvp + CKV_);
            ulonglong2 kv2 = *(const ulonglong2*)(kvp + 2 * CKV_);
            fma2p(a0l, ww, kv0.x); fma2p(a0h, ww, kv0.y);
            fma2p(a1l, ww, kv1.x); fma2p(a1h, ww, kv1.y);
            fma2p(a2l, ww, kv2.x); fma2p(a2h, ww, kv2.y);
        }
        // dots (K half produces the valid value; reduce over the 16-lane half)
        u64 t0 = mul2p(qq.x, a0l); fma2p(t0, qq.y, a0h);
        u64 t1 = mul2p(qq.x, a1l); fma2p(t1, qq.y, a1h);
        u64 t2 = mul2p(qq.x, a2l); fma2p(t2, qq.y, a2h);
        float2 f0 = unpack2p(t0), f1 = unpack2p(t1), f2 = unpack2p(t2);
        float d0 = f0.x + f0.y, d1 = f1.x + f1.y, d2 = f2.x + f2.y;
#pragma unroll
        for (int s = 8; s > 0; s >>= 1) {
            d0 += __shfl_xor_sync(0xffffffffu, d0, s);
            d1 += __shfl_xor_sync(0xffffffffu, d1, s);
            d2 += __shfl_xor_sync(0xffffffffu, d2, s);
        }
        float l0 = __shfl_sync(0xffffffffu, d0, 0) * SCALE_ * sw;
        float l1 = __shfl_sync(0xffffffffu, d1, 0) * SCALE_ * sw;
        float l2 = __shfl_sync(0xffffffffu, d2, 0) * SCALE_ * sw;

        // online softmax per t (packed o-updates)
        {
            float mn = fmaxf(m0, l0);
            float c1 = __expf(m0 - mn), c2 = __expf(l0 - mn);
            s0 = s0 * c1 + c2;
            u64 c1p = pack2p(c1, c1), c2p = pack2p(c2, c2);
            o0l = mul2p(o0l, c1p); fma2p(o0l, c2p, a0l);
            o0h = mul2p(o0h, c1p); fma2p(o0h, c2p, a0h);
            m0 = mn;
        }
        {
            float mn = fmaxf(m1, l1);
            float c1 = __expf(m1 - mn), c2 = __expf(l1 - mn);
            s1 = s1 * c1 + c2;
            u64 c1p = pack2p(c1, c1), c2p = pack2p(c2, c2);
            o1l = mul2p(o1l, c1p); fma2p(o1l, c2p, a1l);
            o1h = mul2p(o1h, c1p); fma2p(o1h, c2p, a1h);
            m1 = mn;
        }
        {
            float mn = fmaxf(m2, l2);
            float c1 = __expf(m2 - mn), c2 = __expf(l2 - mn);
            s2 = s2 * c1 + c2;
            u64 c1p = pack2p(c1, c1), c2p = pack2p(c2, c2);
            o2l = mul2p(o2l, c1p); fma2p(o2l, c2p, a2l);
            o2h = mul2p(o2h, c1p); fma2p(o2h, c2p, a2h);
            m2 = mn;
        }
    }

    if (part == 1) {
        const float third = 1.0f / 3.0f;
        float i0 = third / s0, i1 = third / s1, i2 = third / s2;
        u64 i0p = pack2p(i0, i0), i1p = pack2p(i1, i1), i2p = pack2p(i2, i2);
        u64 rl = mul2p(o0l, i0p); fma2p(rl, o1l, i1p); fma2p(rl, o2l, i2p);
        u64 rh = mul2p(o0h, i0p); fma2p(rh, o1h, i1p); fma2p(rh, o2h, i2p);
        float2 flo = unpack2p(rl), fhi = unpack2p(rh);

        __nv_bfloat16 hx, lx, hy, ly, hz, lz, hw, lw;
        split_bf(flo.x, hx, lx); split_bf(flo.y, hy, ly);
        split_bf(fhi.x, hz, lz); split_bf(fhi.y, hw, lw);
        int oidx = bn * C_ + h * DH_ + ch;
        __nv_bfloat162 hi01(hx, hy), hi23(hz, hw);
        __nv_bfloat162 lo01(lx, ly), lo23(lz, lw);
        uint2 hpack, lpack;
        hpack.x = *(uint32_t*)&hi01; hpack.y = *(uint32_t*)&hi23;
        lpack.x = *(uint32_t*)&lo01; lpack.y = *(uint32_t*)&lo23;
        *(uint2*)(g_ahi + oidx) = hpack;
        *(uint2*)(g_alo + oidx) = lpack;
    }
}

// ---------------- launch ----------------------------------------------------------
extern "C" void kernel_launch(void* const* d_in, const int* in_sizes, int n_in,
                              void* d_out, int out_size)
{
    const float* x     = (const float*)d_in[0];
    const float* mask  = (const float*)d_in[1];
    const float* Wq    = (const float*)d_in[2];
    const float* Wk    = (const float*)d_in[3];
    const float* Wv    = (const float*)d_in[4];
    const float* Woff  = (const float*)d_in[5];
    const float* boff  = (const float*)d_in[6];
    const float* Wproj = (const float*)d_in[7];
    const float* bproj = (const float*)d_in[8];
    const float* suppr = (const float*)d_in[9];
    float* out = (float*)d_out;

    cudaFuncSetAttribute(gemm_merged_kernel,
                         cudaFuncAttributeMaxDynamicSharedMemorySize, MSMEM);
    cudaFuncSetAttribute(gemm_proj_kernel,
                         cudaFuncAttributeMaxDynamicSharedMemorySize, 4 * QTILE);

    conv_x_kernel<<<(MKV_ * C_ / 4 + 255) / 256, 256>>>(x);
    tpose_split_all_kernel<<<dim3(C_ / 32, C_ / 32, 5), dim3(32, 8)>>>(
        Wq, Wk, Wv, Wproj, Woff, boff);

    gemm_merged_kernel<<<QO_BLOCKS + 648, 256, MSMEM>>>();

    attn_kernel<<<BN_, 384>>>(mask, suppr);

    gemm_proj_kernel<<<dim3(C_ / 128, BN_ / 128), 256, 4 * QTILE>>>(bproj, out);
}

// round 15
// speedup vs baseline: 1.1397x; 1.1397x over previous
#include <cuda_runtime.h>
#include <cuda_bf16.h>
#include <cuda_fp16.h>
#include <cstdint>
#include <math.h>

#define B_  4
#define N_  576
#define T_  3
#define C_  768
#define H_  12
#define P_  9
#define DH_ 64
#define HP_ 24
#define SCALE_ 0.125f
#define BN_ (B_ * N_)
#define CKV_ (2 * C_)       // 1536
#define MKV_ (BN_ * T_)     // 6912
#define NOFF_ (H_ * P_ * 2) // 216
#define NQOFF_ 1024         // 768 (q) + 256 (off padded)

typedef unsigned long long u64;

// ---------------- scratch (device globals) -----------------------------------
__device__ __half g_xh[MKV_ * C_];        // x in fp16
__device__ __half g_wkvT[CKV_ * C_];      // [n][k]; n<768: Wk, else Wv (fp16)
__device__ __nv_bfloat16 g_qbf_hi[BN_ * C_];
__device__ __nv_bfloat16 g_qbf_lo[BN_ * C_];
__device__ __nv_bfloat16 g_wqoffT_hi[NQOFF_ * C_];
__device__ __nv_bfloat16 g_wqoffT_lo[NQOFF_ * C_];
__device__ __half g_wprojT_h[C_ * C_];    // Wproj^T fp16
__device__ __half g_pahi[BN_ * C_];       // attn out fp16 hi
__device__ __half g_palo[BN_ * C_];       // attn out fp16 lo
__device__ float g_bias_qoff[NQOFF_];

__device__ __half g_kv[MKV_ * CKV_];      // fp16 KV
__device__ float g_qoff[BN_ * NQOFF_];

// ---------------- PTX helpers ---------------------------------------------------
__device__ __forceinline__ uint32_t smem_to_u32(const void* p) {
    uint32_t a;
    asm("{ .reg .u64 t; cvta.to.shared.u64 t, %1; cvt.u32.u64 %0, t; }"
        : "=r"(a) : "l"(p));
    return a;
}
__device__ __forceinline__ void cp16(uint32_t dst, const void* src) {
    asm volatile("cp.async.cg.shared.global [%0], [%1], 16;"
                 :: "r"(dst), "l"(src));
}
#define CP_COMMIT() asm volatile("cp.async.commit_group;" ::: "memory")
#define CP_WAIT0()  asm volatile("cp.async.wait_group 0;" ::: "memory")
#define CP_WAIT1()  asm volatile("cp.async.wait_group 1;" ::: "memory")
#define CP_WAIT2()  asm volatile("cp.async.wait_group 2;" ::: "memory")

__device__ __forceinline__ void ldm4(uint32_t* r, uint32_t addr) {
    asm volatile("ldmatrix.sync.aligned.m8n8.x4.shared.b16 {%0,%1,%2,%3}, [%4];"
                 : "=r"(r[0]), "=r"(r[1]), "=r"(r[2]), "=r"(r[3]) : "r"(addr));
}
__device__ __forceinline__ void mma_bf16(float* c, const uint32_t* a,
                                         uint32_t b0, uint32_t b1) {
    asm volatile(
        "mma.sync.aligned.m16n8k16.row.col.f32.bf16.bf16.f32 "
        "{%0,%1,%2,%3}, {%4,%5,%6,%7}, {%8,%9}, {%0,%1,%2,%3};"
        : "+f"(c[0]), "+f"(c[1]), "+f"(c[2]), "+f"(c[3])
        : "r"(a[0]), "r"(a[1]), "r"(a[2]), "r"(a[3]), "r"(b0), "r"(b1));
}
__device__ __forceinline__ void mma_fp16(float* c, const uint32_t* a,
                                         uint32_t b0, uint32_t b1) {
    asm volatile(
        "mma.sync.aligned.m16n8k16.row.col.f32.f16.f16.f32 "
        "{%0,%1,%2,%3}, {%4,%5,%6,%7}, {%8,%9}, {%0,%1,%2,%3};"
        : "+f"(c[0]), "+f"(c[1]), "+f"(c[2]), "+f"(c[3])
        : "r"(a[0]), "r"(a[1]), "r"(a[2]), "r"(a[3]), "r"(b0), "r"(b1));
}

// packed math
__device__ __forceinline__ void fma2p(u64& d, u64 a, u64 b) {
    asm("fma.rn.f32x2 %0, %1, %2, %0;" : "+l"(d) : "l"(a), "l"(b));
}
__device__ __forceinline__ u64 mul2p(u64 a, u64 b) {
    u64 d; asm("mul.rn.f32x2 %0, %1, %2;" : "=l"(d) : "l"(a), "l"(b)); return d;
}
__device__ __forceinline__ u64 pack2p(float lo, float hi) {
    u64 d; asm("mov.b64 %0, {%1, %2};" : "=l"(d) : "f"(lo), "f"(hi)); return d;
}
__device__ __forceinline__ float2 unpack2p(u64 v) {
    float2 f; asm("mov.b64 {%0, %1}, %2;" : "=f"(f.x), "=f"(f.y) : "l"(v)); return f;
}
__device__ __forceinline__ void hfma2(uint32_t& d, uint32_t a, uint32_t b) {
    asm("fma.rn.f16x2 %0, %1, %2, %0;" : "+r"(d) : "r"(a), "r"(b));
}

// ---------------- prep kernels ---------------------------------------------------
__device__ __forceinline__ void split_bf(float v, __nv_bfloat16& hi, __nv_bfloat16& lo) {
    hi = __float2bfloat16(v);
    lo = __float2bfloat16(v - __bfloat162float(hi));
}
__device__ __forceinline__ void split_h(float v, __half& hi, __half& lo) {
    hi = __float2half_rn(v);
    lo = __float2half_rn(v - __half2float(hi));
}

__global__ void conv_x_kernel(const float* __restrict__ x) {
    int idx = blockIdx.x * blockDim.x + threadIdx.x;
    if (idx >= MKV_ * C_ / 4) return;
    float4 v = ((const float4*)x)[idx];
    ((__half2*)g_xh)[idx * 2]     = __floats2half2_rn(v.x, v.y);
    ((__half2*)g_xh)[idx * 2 + 1] = __floats2half2_rn(v.z, v.w);

    int token = idx / (C_ / 4);
    if (token % T_ == 1) {
        int bn = token / T_;
        int c4 = idx % (C_ / 4);
        int qidx = bn * (C_ / 4) + c4;
        __nv_bfloat16 h0, l0, h1, l1, h2, l2, h3, l3;
        split_bf(v.x, h0, l0); split_bf(v.y, h1, l1);
        split_bf(v.z, h2, l2); split_bf(v.w, h3, l3);
        ((__nv_bfloat162*)g_qbf_hi)[qidx * 2]     = __nv_bfloat162(h0, h1);
        ((__nv_bfloat162*)g_qbf_hi)[qidx * 2 + 1] = __nv_bfloat162(h2, h3);
        ((__nv_bfloat162*)g_qbf_lo)[qidx * 2]     = __nv_bfloat162(l0, l1);
        ((__nv_bfloat162*)g_qbf_lo)[qidx * 2 + 1] = __nv_bfloat162(l2, l3);
    }
}

__global__ void tpose_split_all_kernel(
    const float* __restrict__ Wq, const float* __restrict__ Wk,
    const float* __restrict__ Wv, const float* __restrict__ Wproj,
    const float* __restrict__ Woff, const float* __restrict__ boff)
{
    if (blockIdx.z == 0 && blockIdx.x == 0 && blockIdx.y == 0) {
        int t = threadIdx.y * 32 + threadIdx.x;
        for (int i = t; i < NQOFF_; i += 256)
            g_bias_qoff[i] = (i >= 768 && i < 768 + NOFF_) ? boff[i - 768] : 0.f;
    }

    const float* src;
    __half* dh = nullptr;
    __nv_bfloat16 *dhi = nullptr, *dlo = nullptr;
    int N, dstRows;
    switch (blockIdx.z) {
        case 0: src = Wq;    dhi = g_wqoffT_hi; dlo = g_wqoffT_lo; N = C_; dstRows = C_; break;
        case 1: src = Wk;    dh = g_wkvT;                 N = C_;   dstRows = C_;  break;
        case 2: src = Wv;    dh = g_wkvT + (long)C_ * C_; N = C_;   dstRows = C_;  break;
        case 3: src = Wproj; dh = g_wprojT_h;             N = C_;   dstRows = C_;  break;
        default: src = Woff; dhi = g_wqoffT_hi + (long)768 * C_;
                             dlo = g_wqoffT_lo + (long)768 * C_;   N = NOFF_; dstRows = 256; break;
    }
    int n0 = blockIdx.x * 32, k0 = blockIdx.y * 32;
    if (n0 >= dstRows) return;

    __shared__ float tile[32][33];
    int tx = threadIdx.x, ty = threadIdx.y;
#pragma unroll
    for (int j = 0; j < 4; j++) {
        int k = k0 + ty + j * 8, n = n0 + tx;
        tile[ty + j * 8][tx] = (n < N) ? src[(long)k * N + n] : 0.f;
    }
    __syncthreads();
#pragma unroll
    for (int j = 0; j < 4; j++) {
        int n = n0 + ty + j * 8, k = k0 + tx;
        if (n < dstRows) {
            float v = tile[tx][ty + j * 8];
            if (dh) {
                dh[(long)n * C_ + k] = __float2half_rn(v);
            } else {
                __nv_bfloat16 hi, lo;
                split_bf(v, hi, lo);
                dhi[(long)n * C_ + k] = hi;
                dlo[(long)n * C_ + k] = lo;
            }
        }
    }
}

// ---------------- GEMM bodies: 256 threads, 2 CTAs/SM -----------------------------
#define FTILE 16384
#define FSTAGE (2 * FTILE)
#define MSMEM  (3 * FSTAGE)   // 98304

// KV: C(half) = Ah @ Bh^T, 3-stage pipeline
__device__ __forceinline__ void gemm_fp16_body256(
    const __half* __restrict__ Ah, long lda,
    const __half* __restrict__ Bh,
    __half* __restrict__ C, int ldc, int K,
    int row0, int col0, char* smem)
{
    uint32_t sb = smem_to_u32(smem);
    int tid = threadIdx.x;
    int wid = tid >> 5, lane = tid & 31;
    int warp_m = wid & 3;
    int warp_n = wid >> 2;
    const int NKITER = K / 64;

    int rr[4], cc[4], doff[4];
#pragma unroll
    for (int j = 0; j < 4; j++) {
        int u = tid + j * 256;
        int r = u >> 3, cu = u & 7;
        rr[j] = r; cc[j] = cu;
        doff[j] = ((r << 3) + (cu ^ (r & 7))) << 4;
    }

    const __half* gp[2] = {Ah, Bh};
    long  st[2] = {lda, (long)K};
    int   rb[2] = {row0, col0};

#pragma unroll
    for (int s = 0; s < 2; s++) {
        uint32_t sstage = sb + s * FSTAGE;
        int k0 = s * 64;
#pragma unroll
        for (int a = 0; a < 2; a++) {
            uint32_t sdst = sstage + a * FTILE;
            const __half* g = gp[a];
#pragma unroll
            for (int j = 0; j < 4; j++)
                cp16(sdst + doff[j],
                     g + (long)(rb[a] + rr[j]) * st[a] + k0 + cc[j] * 8);
        }
        CP_COMMIT();
    }

    float acc[2][8][4];
#pragma unroll
    for (int mf = 0; mf < 2; mf++)
#pragma unroll
        for (int nf = 0; nf < 8; nf++)
#pragma unroll
            for (int e = 0; e < 4; e++) acc[mf][nf][e] = 0.f;

    int a_r = warp_m * 32 + (lane & 7) + ((lane & 8) ? 8 : 0);
    int a_usel = (lane & 16) ? 1 : 0;
    int b_rbase = warp_n * 64 + (lane & 7) + ((lane & 16) ? 8 : 0);
    int b_usel = (lane & 8) ? 1 : 0;

    int bufc = 0, bufn = 2;
    for (int kc = 0; kc < NKITER; kc++) {
        if (kc + 2 < NKITER) {
            uint32_t sstage = sb + bufn * FSTAGE;
            int k0 = (kc + 2) * 64;
#pragma unroll
            for (int a = 0; a < 2; a++) {
                uint32_t sdst = sstage + a * FTILE;
                const __half* g = gp[a];
#pragma unroll
                for (int j = 0; j < 4; j++)
                    cp16(sdst + doff[j],
                         g + (long)(rb[a] + rr[j]) * st[a] + k0 + cc[j] * 8);
            }
            CP_COMMIT();
            CP_WAIT2();
        } else if (kc + 1 < NKITER) {
            CP_WAIT1();
        } else {
            CP_WAIT0();
        }
        __syncthreads();

        uint32_t s = sb + bufc * FSTAGE;
        uint32_t sA = s, sB = s + FTILE;

#pragma unroll
        for (int ks = 0; ks < 4; ks++) {
            uint32_t af[2][4];
#pragma unroll
            for (int mf = 0; mf < 2; mf++) {
                int r = a_r + mf * 16;
                int u = ks * 2 + a_usel;
                uint32_t off = (uint32_t)(((r << 3) + (u ^ (r & 7))) << 4);
                ldm4(af[mf], sA + off);
            }
#pragma unroll
            for (int np = 0; np < 4; np++) {
                uint32_t bf[4];
                int r = b_rbase + np * 16;
                int u = ks * 2 + b_usel;
                uint32_t off = (uint32_t)(((r << 3) + (u ^ (r & 7))) << 4);
                ldm4(bf, sB + off);
#pragma unroll
                for (int mf = 0; mf < 2; mf++)
#pragma unroll
                    for (int jj = 0; jj < 2; jj++)
                        mma_fp16(acc[mf][np * 2 + jj], af[mf],
                                 bf[jj * 2], bf[jj * 2 + 1]);
            }
        }
        __syncthreads();
        bufc = (bufc == 2) ? 0 : bufc + 1;
        bufn = (bufn == 2) ? 0 : bufn + 1;
    }

#pragma unroll
    for (int mf = 0; mf < 2; mf++) {
        int m = row0 + warp_m * 32 + mf * 16 + (lane >> 2);
#pragma unroll
        for (int nf = 0; nf < 8; nf++) {
            int n = col0 + warp_n * 64 + nf * 8 + (lane & 3) * 2;
            __half2 v0 = __floats2half2_rn(acc[mf][nf][0], acc[mf][nf][1]);
            __half2 v1 = __floats2half2_rn(acc[mf][nf][2], acc[mf][nf][3]);
            *(__half2*)(C + (long)m * ldc + n)       = v0;
            *(__half2*)(C + (long)(m + 8) * ldc + n) = v1;
        }
    }
}

// fp16 2-term: C(float) = (Ahi+Alo) @ Bh^T + bias  (projection)
#define PSTAGE (3 * FTILE)
#define PSMEM  (2 * PSTAGE)   // 98304
__device__ __forceinline__ void gemm_fp16x2_body256(
    const __half* __restrict__ Ahi,
    const __half* __restrict__ Alo, long lda,
    const __half* __restrict__ Bh,
    const float* __restrict__ bias,
    float* __restrict__ C, int ldc, int K,
    int row0, int col0, char* smem)
{
    uint32_t sb = smem_to_u32(smem);
    int tid = threadIdx.x;
    int wid = tid >> 5, lane = tid & 31;
    int warp_m = wid & 3;
    int warp_n = wid >> 2;
    const int NKITER = K / 64;

    int rr[4], cc[4], doff[4];
#pragma unroll
    for (int j = 0; j < 4; j++) {
        int u = tid + j * 256;
        int r = u >> 3, cu = u & 7;
        rr[j] = r; cc[j] = cu;
        doff[j] = ((r << 3) + (cu ^ (r & 7))) << 4;
    }

    const __half* gp[3] = {Ahi, Alo, Bh};
    long  st[3] = {lda, lda, (long)K};
    int   rb[3] = {row0, row0, col0};

    // stage 0
#pragma unroll
    for (int a = 0; a < 3; a++) {
        uint32_t sdst = sb + a * FTILE;
        const __half* g = gp[a];
#pragma unroll
        for (int j = 0; j < 4; j++)
            cp16(sdst + doff[j], g + (long)(rb[a] + rr[j]) * st[a] + cc[j] * 8);
    }
    CP_COMMIT();

    float acc[2][8][4];
#pragma unroll
    for (int mf = 0; mf < 2; mf++)
#pragma unroll
        for (int nf = 0; nf < 8; nf++)
#pragma unroll
            for (int e = 0; e < 4; e++) acc[mf][nf][e] = 0.f;

    int a_r = warp_m * 32 + (lane & 7) + ((lane & 8) ? 8 : 0);
    int a_usel = (lane & 16) ? 1 : 0;
    int b_rbase = warp_n * 64 + (lane & 7) + ((lane & 16) ? 8 : 0);
    int b_usel = (lane & 8) ? 1 : 0;

    for (int kc = 0; kc < NKITER; kc++) {
        if (kc + 1 < NKITER) {
            uint32_t sstage = sb + ((kc + 1) & 1) * PSTAGE;
            int k0 = (kc + 1) * 64;
#pragma unroll
            for (int a = 0; a < 3; a++) {
                uint32_t sdst = sstage + a * FTILE;
                const __half* g = gp[a];
#pragma unroll
                for (int j = 0; j < 4; j++)
                    cp16(sdst + doff[j],
                         g + (long)(rb[a] + rr[j]) * st[a] + k0 + cc[j] * 8);
            }
            CP_COMMIT();
            CP_WAIT1();
        } else {
            CP_WAIT0();
        }
        __syncthreads();

        uint32_t s = sb + (kc & 1) * PSTAGE;
        uint32_t sAhi = s, sAlo = s + FTILE, sB = s + 2 * FTILE;

#pragma unroll
        for (int ks = 0; ks < 4; ks++) {
            uint32_t ah[2][4], al[2][4];
#pragma unroll
            for (int mf = 0; mf < 2; mf++) {
                int r = a_r + mf * 16;
                int u = ks * 2 + a_usel;
                uint32_t off = (uint32_t)(((r << 3) + (u ^ (r & 7))) << 4);
                ldm4(ah[mf], sAhi + off);
                ldm4(al[mf], sAlo + off);
            }
#pragma unroll
            for (int np = 0; np < 4; np++) {
                uint32_t bf[4];
                int r = b_rbase + np * 16;
                int u = ks * 2 + b_usel;
                uint32_t off = (uint32_t)(((r << 3) + (u ^ (r & 7))) << 4);
                ldm4(bf, sB + off);
#pragma unroll
                for (int mf = 0; mf < 2; mf++)
#pragma unroll
                    for (int jj = 0; jj < 2; jj++) {
                        mma_fp16(acc[mf][np * 2 + jj], ah[mf],
                                 bf[jj * 2], bf[jj * 2 + 1]);
                        mma_fp16(acc[mf][np * 2 + jj], al[mf],
                                 bf[jj * 2], bf[jj * 2 + 1]);
                    }
            }
        }
        __syncthreads();
    }

#pragma unroll
    for (int mf = 0; mf < 2; mf++) {
        int m = row0 + warp_m * 32 + mf * 16 + (lane >> 2);
#pragma unroll
        for (int nf = 0; nf < 8; nf++) {
            int n = col0 + warp_n * 64 + nf * 8 + (lane & 3) * 2;
            float2 v0, v1;
            v0.x = acc[mf][nf][0]; v0.y = acc[mf][nf][1];
            v1.x = acc[mf][nf][2]; v1.y = acc[mf][nf][3];
            float bx = bias[n], by = bias[n + 1];
            v0.x += bx; v0.y += by;
            v1.x += bx; v1.y += by;
            *(float2*)(C + (long)m * ldc + n)       = v0;
            *(float2*)(C + (long)(m + 8) * ldc + n) = v1;
        }
    }
}

#define QTILE 16384
__device__ __forceinline__ void gemm_bf16x3_body256(
    const __nv_bfloat16* __restrict__ Ahi,
    const __nv_bfloat16* __restrict__ Alo, long lda,
    const __nv_bfloat16* __restrict__ Bhi,
    const __nv_bfloat16* __restrict__ Blo,
    const float* __restrict__ bias,
    float* __restrict__ C, int ldc, int Nstore, int K,
    int row0, int col0, char* smem)
{
    uint32_t sb = smem_to_u32(smem);
    int tid = threadIdx.x;
    int wid = tid >> 5, lane = tid & 31;
    int warp_m = wid & 3;
    int warp_n = wid >> 2;
    const int NKITER = K / 64;

    int rr[4], cc[4], doff[4];
#pragma unroll
    for (int j = 0; j < 4; j++) {
        int u = tid + j * 256;
        int r = u >> 3, cu = u & 7;
        rr[j] = r; cc[j] = cu;
        doff[j] = ((r << 3) + (cu ^ (r & 7))) << 4;
    }

    const __nv_bfloat16* gp[4] = {Ahi, Alo, Bhi, Blo};
    long  st[4] = {lda, lda, (long)K, (long)K};
    int   rb[4] = {row0, row0, col0, col0};

    float acc[2][8][4];
#pragma unroll
    for (int mf = 0; mf < 2; mf++)
#pragma unroll
        for (int nf = 0; nf < 8; nf++)
#pragma unroll
            for (int e = 0; e < 4; e++) acc[mf][nf][e] = 0.f;

    int a_r = warp_m * 32 + (lane & 7) + ((lane & 8) ? 8 : 0);
    int a_usel = (lane & 16) ? 1 : 0;
    int b_rbase = warp_n * 64 + (lane & 7) + ((lane & 16) ? 8 : 0);
    int b_usel = (lane & 8) ? 1 : 0;

    for (int kc = 0; kc < NKITER; kc++) {
        int k0 = kc * 64;
#pragma unroll
        for (int a = 0; a < 4; a++) {
            uint32_t sdst = sb + a * QTILE;
            const __nv_bfloat16* g = gp[a];
#pragma unroll
            for (int j = 0; j < 4; j++)
                cp16(sdst + doff[j],
                     g + (long)(rb[a] + rr[j]) * st[a] + k0 + cc[j] * 8);
        }
        CP_COMMIT();
        CP_WAIT0();
        __syncthreads();

        uint32_t sAhi = sb, sAlo = sb + QTILE;
        uint32_t sBhi = sb + 2 * QTILE, sBlo = sb + 3 * QTILE;

#pragma unroll
        for (int ks = 0; ks < 4; ks++) {
            uint32_t ah[2][4], al[2][4];
#pragma unroll
            for (int mf = 0; mf < 2; mf++) {
                int r = a_r + mf * 16;
                int u = ks * 2 + a_usel;
                uint32_t off = (uint32_t)(((r << 3) + (u ^ (r & 7))) << 4);
                ldm4(ah[mf], sAhi + off);
                ldm4(al[mf], sAlo + off);
            }
#pragma unroll
            for (int np = 0; np < 4; np++) {
                uint32_t bh[4], bl[4];
                int r = b_rbase + np * 16;
                int u = ks * 2 + b_usel;
                uint32_t off = (uint32_t)(((r << 3) + (u ^ (r & 7))) << 4);
                ldm4(bh, sBhi + off);
                ldm4(bl, sBlo + off);
#pragma unroll
                for (int mf = 0; mf < 2; mf++)
#pragma unroll
                    for (int jj = 0; jj < 2; jj++) {
                        float* a4 = acc[mf][np * 2 + jj];
                        mma_bf16(a4, ah[mf], bh[jj * 2], bh[jj * 2 + 1]);
                        mma_bf16(a4, ah[mf], bl[jj * 2], bl[jj * 2 + 1]);
                        mma_bf16(a4, al[mf], bh[jj * 2], bh[jj * 2 + 1]);
                    }
            }
        }
        __syncthreads();
    }

#pragma unroll
    for (int mf = 0; mf < 2; mf++) {
        int m = row0 + warp_m * 32 + mf * 16 + (lane >> 2);
#pragma unroll
        for (int nf = 0; nf < 8; nf++) {
            int n = col0 + warp_n * 64 + nf * 8 + (lane & 3) * 2;
            if (n < Nstore) {
                float2 v0, v1;
                v0.x = acc[mf][nf][0]; v0.y = acc[mf][nf][1];
                v1.x = acc[mf][nf][2]; v1.y = acc[mf][nf][3];
                if (bias) {
                    float bx = bias[n], by = bias[n + 1];
                    v0.x += bx; v0.y += by;
                    v1.x += bx; v1.y += by;
                }
                *(float2*)(C + (long)m * ldc + n)       = v0;
                *(float2*)(C + (long)(m + 8) * ldc + n) = v1;
            }
        }
    }
}

#define QO_BLOCKS 144
__global__ __launch_bounds__(256, 2)
void gemm_merged_kernel()
{
    extern __shared__ char smem[];
    int bid = blockIdx.x;
    if (bid < QO_BLOCKS) {
        int bx = bid % 8, by = bid / 8;
        gemm_bf16x3_body256(g_qbf_hi, g_qbf_lo, C_,
                            g_wqoffT_hi, g_wqoffT_lo, g_bias_qoff,
                            g_qoff, NQOFF_, 768 + NOFF_, C_,
                            by * 128, bx * 128, smem);
    } else {
        int b2 = bid - QO_BLOCKS;
        int bx = b2 % 12, by = b2 / 12;
        gemm_fp16_body256(g_xh, C_, g_wkvT,
                          g_kv, CKV_, C_, by * 128, bx * 128, smem);
    }
}

__global__ __launch_bounds__(256, 2)
void gemm_proj_kernel(const float* __restrict__ bias, float* __restrict__ C)
{
    extern __shared__ char smem[];
    gemm_fp16x2_body256(g_pahi, g_palo, C_, g_wprojT_h, bias,
                        C, C_, C_, blockIdx.y * 128, blockIdx.x * 128, smem);
}

// ---------------- deformable attention core ---------------------------------------
// fp16 KV loads + HFMA2 bilinear accumulate; fp32 packed dot/softmax.
__global__ __launch_bounds__(384, 2) void attn_kernel(
    const float* __restrict__ mask,
    const float* __restrict__ suppress_p)
{
    int bn = blockIdx.x;
    int b  = bn / N_;
    int n  = bn % N_;
    int h    = threadIdx.x >> 5;
    int lane = threadIdx.x & 31;
    int part = lane >> 4;
    int ch   = (lane & 15) * 4;

    float suppress = *suppress_p;
    float mk  = mask[bn];
    float sw  = 1.f - suppress * mk;
    float moff = suppress * mk * 0.1f;

    float refx = (float)(n % HP_) * (2.f / 23.f) - 1.f;
    float refy = (float)(n / HP_) * (2.f / 23.f) - 1.f;

    const float* rowbase = g_qoff + bn * NQOFF_;
    ulonglong2 qq = *(const ulonglong2*)(rowbase + h * DH_ + ch);

    const float* offrow = rowbase + 768 + h * (P_ * 2);
    float offv = (lane < P_ * 2) ? offrow[lane] : 0.f;

    int base_part = h * DH_ + part * C_ + ch;
    int pixbase = b * N_;

    float m0 = -1e30f, m1 = -1e30f, m2 = -1e30f;
    float s0 = 0.f, s1 = 0.f, s2 = 0.f;
    u64 o0l = 0, o0h = 0, o1l = 0, o1h = 0, o2l = 0, o2h = 0;

#pragma unroll
    for (int p = 0; p < P_; p++) {
        float ox = __shfl_sync(0xffffffffu, offv, 2 * p)     - moff;
        float oy = __shfl_sync(0xffffffffu, offv, 2 * p + 1) - moff;
        float xs = (refx + ox + 1.f) * 11.5f;
        float ys = (refy + oy + 1.f) * 11.5f;
        float x0f = floorf(xs), y0f = floorf(ys);
        int   x0 = (int)x0f,  y0 = (int)y0f;
        float wx1 = xs - x0f, wy1 = ys - y0f;
        float wx0 = 1.f - wx1, wy0 = 1.f - wy1;

        // fp16 bilinear accumulators (2 half2 per t)
        uint32_t h0x = 0, h0y = 0, h1x = 0, h1y = 0, h2x = 0, h2y = 0;
#pragma unroll
        for (int c = 0; c < 4; c++) {
            int dx = c & 1, dy = c >> 1;
            int ix = x0 + dx, iy = y0 + dy;
            float valid = (ix >= 0 && ix < HP_ && iy >= 0 && iy < HP_) ? 1.f : 0.f;
            float w = (dx ? wx1 : wx0) * (dy ? wy1 : wy0) * valid;
            __half2 wh = __float2half2_rn(w);
            uint32_t w2 = *(uint32_t*)&wh;
            int ixc = min(max(ix, 0), HP_ - 1);
            int iyc = min(max(iy, 0), HP_ - 1);
            int idx = (pixbase + iyc * HP_ + ixc) * (T_ * CKV_) + base_part;
            const __half* kvp = g_kv + idx;
            uint2 kv0 = *(const uint2*)(kvp);
            uint2 kv1 = *(const uint2*)(kvp + CKV_);
            uint2 kv2 = *(const uint2*)(kvp + 2 * CKV_);
            hfma2(h0x, w2, kv0.x); hfma2(h0y, w2, kv0.y);
            hfma2(h1x, w2, kv1.x); hfma2(h1y, w2, kv1.y);
            hfma2(h2x, w2, kv2.x); hfma2(h2y, w2, kv2.y);
        }
        // convert once per point to fp32 packed
        float2 f0a = __half22float2(*(__half2*)&h0x);
        float2 f0b = __half22float2(*(__half2*)&h0y);
        float2 f1a = __half22float2(*(__half2*)&h1x);
        float2 f1b = __half22float2(*(__half2*)&h1y);
        float2 f2a = __half22float2(*(__half2*)&h2x);
        float2 f2b = __half22float2(*(__half2*)&h2y);
        u64 a0l = pack2p(f0a.x, f0a.y), a0h = pack2p(f0b.x, f0b.y);
        u64 a1l = pack2p(f1a.x, f1a.y), a1h = pack2p(f1b.x, f1b.y);
        u64 a2l = pack2p(f2a.x, f2a.y), a2h = pack2p(f2b.x, f2b.y);

        // dots (K half supplies valid values)
        u64 t0 = mul2p(qq.x, a0l); fma2p(t0, qq.y, a0h);
        u64 t1 = mul2p(qq.x, a1l); fma2p(t1, qq.y, a1h);
        u64 t2 = mul2p(qq.x, a2l); fma2p(t2, qq.y, a2h);
        float2 g0 = unpack2p(t0), g1 = unpack2p(t1), g2 = unpack2p(t2);
        float d0 = g0.x + g0.y, d1 = g1.x + g1.y, d2 = g2.x + g2.y;
#pragma unroll
        for (int s = 8; s > 0; s >>= 1) {
            d0 += __shfl_xor_sync(0xffffffffu, d0, s);
            d1 += __shfl_xor_sync(0xffffffffu, d1, s);
            d2 += __shfl_xor_sync(0xffffffffu, d2, s);
        }
        float l0 = __shfl_sync(0xffffffffu, d0, 0) * SCALE_ * sw;
        float l1 = __shfl_sync(0xffffffffu, d1, 0) * SCALE_ * sw;
        float l2 = __shfl_sync(0xffffffffu, d2, 0) * SCALE_ * sw;

        {
            float mn = fmaxf(m0, l0);
            float c1 = __expf(m0 - mn), c2 = __expf(l0 - mn);
            s0 = s0 * c1 + c2;
            u64 c1p = pack2p(c1, c1), c2p = pack2p(c2, c2);
            o0l = mul2p(o0l, c1p); fma2p(o0l, c2p, a0l);
            o0h = mul2p(o0h, c1p); fma2p(o0h, c2p, a0h);
            m0 = mn;
        }
        {
            float mn = fmaxf(m1, l1);
            float c1 = __expf(m1 - mn), c2 = __expf(l1 - mn);
            s1 = s1 * c1 + c2;
            u64 c1p = pack2p(c1, c1), c2p = pack2p(c2, c2);
            o1l = mul2p(o1l, c1p); fma2p(o1l, c2p, a1l);
            o1h = mul2p(o1h, c1p); fma2p(o1h, c2p, a1h);
            m1 = mn;
        }
        {
            float mn = fmaxf(m2, l2);
            float c1 = __expf(m2 - mn), c2 = __expf(l2 - mn);
            s2 = s2 * c1 + c2;
            u64 c1p = pack2p(c1, c1), c2p = pack2p(c2, c2);
            o2l = mul2p(o2l, c1p); fma2p(o2l, c2p, a2l);
            o2h = mul2p(o2h, c1p); fma2p(o2h, c2p, a2h);
            m2 = mn;
        }
    }

    if (part == 1) {
        const float third = 1.0f / 3.0f;
        float i0 = third / s0, i1 = third / s1, i2 = third / s2;
        u64 i0p = pack2p(i0, i0), i1p = pack2p(i1, i1), i2p = pack2p(i2, i2);
        u64 rl = mul2p(o0l, i0p); fma2p(rl, o1l, i1p); fma2p(rl, o2l, i2p);
        u64 rh = mul2p(o0h, i0p); fma2p(rh, o1h, i1p); fma2p(rh, o2h, i2p);
        float2 flo = unpack2p(rl), fhi = unpack2p(rh);

        __half hx, lx, hy, ly, hz, lz, hw, lw;
        split_h(flo.x, hx, lx); split_h(flo.y, hy, ly);
        split_h(fhi.x, hz, lz); split_h(fhi.y, hw, lw);
        int oidx = bn * C_ + h * DH_ + ch;
        __half2 hiA = __halves2half2(hx, hy), hiB = __halves2half2(hz, hw);
        __half2 loA = __halves2half2(lx, ly), loB = __halves2half2(lz, lw);
        uint2 hpack, lpack;
        hpack.x = *(uint32_t*)&hiA; hpack.y = *(uint32_t*)&hiB;
        lpack.x = *(uint32_t*)&loA; lpack.y = *(uint32_t*)&loB;
        *(uint2*)(g_pahi + oidx) = hpack;
        *(uint2*)(g_palo + oidx) = lpack;
    }
}

// ---------------- launch ----------------------------------------------------------
extern "C" void kernel_launch(void* const* d_in, const int* in_sizes, int n_in,
                              void* d_out, int out_size)
{
    const float* x     = (const float*)d_in[0];
    const float* mask  = (const float*)d_in[1];
    const float* Wq    = (const float*)d_in[2];
    const float* Wk    = (const float*)d_in[3];
    const float* Wv    = (const float*)d_in[4];
    const float* Woff  = (const float*)d_in[5];
    const float* boff  = (const float*)d_in[6];
    const float* Wproj = (const float*)d_in[7];
    const float* bproj = (const float*)d_in[8];
    const float* suppr = (const float*)d_in[9];
    float* out = (float*)d_out;

    cudaFuncSetAttribute(gemm_merged_kernel,
                         cudaFuncAttributeMaxDynamicSharedMemorySize, MSMEM);
    cudaFuncSetAttribute(gemm_proj_kernel,
                         cudaFuncAttributeMaxDynamicSharedMemorySize, PSMEM);

    conv_x_kernel<<<(MKV_ * C_ / 4 + 255) / 256, 256>>>(x);
    tpose_split_all_kernel<<<dim3(C_ / 32, C_ / 32, 5), dim3(32, 8)>>>(
        Wq, Wk, Wv, Wproj, Woff, boff);

    gemm_merged_kernel<<<QO_BLOCKS + 648, 256, MSMEM>>>();

    attn_kernel<<<BN_, 384>>>(mask, suppr);

    gemm_proj_kernel<<<dim3(C_ / 128, BN_ / 128), 256, PSMEM>>>(bproj, out);
}

// round 16
// speedup vs baseline: 1.1832x; 1.0382x over previous
#include <cuda_runtime.h>
#include <cuda_bf16.h>
#include <cuda_fp16.h>
#include <cstdint>
#include <math.h>

#define B_  4
#define N_  576
#define T_  3
#define C_  768
#define H_  12
#define P_  9
#define DH_ 64
#define HP_ 24
#define SCALE_ 0.125f
#define BN_ (B_ * N_)
#define CKV_ (2 * C_)       // 1536
#define MKV_ (BN_ * T_)     // 6912
#define NOFF_ (H_ * P_ * 2) // 216
#define NQOFF_ 1024         // 768 (q) + 256 (off padded)

typedef unsigned long long u64;

// ---------------- scratch (device globals) -----------------------------------
__device__ __half g_xh[MKV_ * C_];        // x in fp16
__device__ __half g_wkvT[CKV_ * C_];      // [n][k]; n<768: Wk, else Wv (fp16)
__device__ __nv_bfloat16 g_qbf_hi[BN_ * C_];
__device__ __nv_bfloat16 g_qbf_lo[BN_ * C_];
__device__ __nv_bfloat16 g_wqoffT_hi[NQOFF_ * C_];
__device__ __nv_bfloat16 g_wqoffT_lo[NQOFF_ * C_];
__device__ __half g_wprojT_h[C_ * C_];    // Wproj^T fp16
__device__ __half g_pahi[BN_ * C_];       // attn out fp16 hi
__device__ __half g_palo[BN_ * C_];       // attn out fp16 lo
__device__ float g_bias_qoff[NQOFF_];

__device__ __half g_kv[MKV_ * CKV_];      // fp16 KV
__device__ float g_qoff[BN_ * NQOFF_];

// ---------------- PTX helpers ---------------------------------------------------
__device__ __forceinline__ uint32_t smem_to_u32(const void* p) {
    uint32_t a;
    asm("{ .reg .u64 t; cvta.to.shared.u64 t, %1; cvt.u32.u64 %0, t; }"
        : "=r"(a) : "l"(p));
    return a;
}
__device__ __forceinline__ void cp16(uint32_t dst, const void* src) {
    asm volatile("cp.async.cg.shared.global [%0], [%1], 16;"
                 :: "r"(dst), "l"(src));
}
#define CP_COMMIT() asm volatile("cp.async.commit_group;" ::: "memory")
#define CP_WAIT0()  asm volatile("cp.async.wait_group 0;" ::: "memory")
#define CP_WAIT1()  asm volatile("cp.async.wait_group 1;" ::: "memory")
#define CP_WAIT2()  asm volatile("cp.async.wait_group 2;" ::: "memory")

__device__ __forceinline__ void ldm4(uint32_t* r, uint32_t addr) {
    asm volatile("ldmatrix.sync.aligned.m8n8.x4.shared.b16 {%0,%1,%2,%3}, [%4];"
                 : "=r"(r[0]), "=r"(r[1]), "=r"(r[2]), "=r"(r[3]) : "r"(addr));
}
__device__ __forceinline__ void mma_bf16(float* c, const uint32_t* a,
                                         uint32_t b0, uint32_t b1) {
    asm volatile(
        "mma.sync.aligned.m16n8k16.row.col.f32.bf16.bf16.f32 "
        "{%0,%1,%2,%3}, {%4,%5,%6,%7}, {%8,%9}, {%0,%1,%2,%3};"
        : "+f"(c[0]), "+f"(c[1]), "+f"(c[2]), "+f"(c[3])
        : "r"(a[0]), "r"(a[1]), "r"(a[2]), "r"(a[3]), "r"(b0), "r"(b1));
}
__device__ __forceinline__ void mma_fp16(float* c, const uint32_t* a,
                                         uint32_t b0, uint32_t b1) {
    asm volatile(
        "mma.sync.aligned.m16n8k16.row.col.f32.f16.f16.f32 "
        "{%0,%1,%2,%3}, {%4,%5,%6,%7}, {%8,%9}, {%0,%1,%2,%3};"
        : "+f"(c[0]), "+f"(c[1]), "+f"(c[2]), "+f"(c[3])
        : "r"(a[0]), "r"(a[1]), "r"(a[2]), "r"(a[3]), "r"(b0), "r"(b1));
}

// packed math
__device__ __forceinline__ void fma2p(u64& d, u64 a, u64 b) {
    asm("fma.rn.f32x2 %0, %1, %2, %0;" : "+l"(d) : "l"(a), "l"(b));
}
__device__ __forceinline__ u64 mul2p(u64 a, u64 b) {
    u64 d; asm("mul.rn.f32x2 %0, %1, %2;" : "=l"(d) : "l"(a), "l"(b)); return d;
}
__device__ __forceinline__ u64 pack2p(float lo, float hi) {
    u64 d; asm("mov.b64 %0, {%1, %2};" : "=l"(d) : "f"(lo), "f"(hi)); return d;
}
__device__ __forceinline__ float2 unpack2p(u64 v) {
    float2 f; asm("mov.b64 {%0, %1}, %2;" : "=f"(f.x), "=f"(f.y) : "l"(v)); return f;
}
__device__ __forceinline__ void hfma2(uint32_t& d, uint32_t a, uint32_t b) {
    asm("fma.rn.f16x2 %0, %1, %2, %0;" : "+r"(d) : "r"(a), "r"(b));
}

// ---------------- prep kernels ---------------------------------------------------
__device__ __forceinline__ void split_bf(float v, __nv_bfloat16& hi, __nv_bfloat16& lo) {
    hi = __float2bfloat16(v);
    lo = __float2bfloat16(v - __bfloat162float(hi));
}
__device__ __forceinline__ void split_h(float v, __half& hi, __half& lo) {
    hi = __float2half_rn(v);
    lo = __float2half_rn(v - __half2float(hi));
}

__global__ void conv_x_kernel(const float* __restrict__ x) {
    int idx = blockIdx.x * blockDim.x + threadIdx.x;
    if (idx >= MKV_ * C_ / 4) return;
    float4 v = ((const float4*)x)[idx];
    ((__half2*)g_xh)[idx * 2]     = __floats2half2_rn(v.x, v.y);
    ((__half2*)g_xh)[idx * 2 + 1] = __floats2half2_rn(v.z, v.w);

    int token = idx / (C_ / 4);
    if (token % T_ == 1) {
        int bn = token / T_;
        int c4 = idx % (C_ / 4);
        int qidx = bn * (C_ / 4) + c4;
        __nv_bfloat16 h0, l0, h1, l1, h2, l2, h3, l3;
        split_bf(v.x, h0, l0); split_bf(v.y, h1, l1);
        split_bf(v.z, h2, l2); split_bf(v.w, h3, l3);
        ((__nv_bfloat162*)g_qbf_hi)[qidx * 2]     = __nv_bfloat162(h0, h1);
        ((__nv_bfloat162*)g_qbf_hi)[qidx * 2 + 1] = __nv_bfloat162(h2, h3);
        ((__nv_bfloat162*)g_qbf_lo)[qidx * 2]     = __nv_bfloat162(l0, l1);
        ((__nv_bfloat162*)g_qbf_lo)[qidx * 2 + 1] = __nv_bfloat162(l2, l3);
    }
}

__global__ void tpose_split_all_kernel(
    const float* __restrict__ Wq, const float* __restrict__ Wk,
    const float* __restrict__ Wv, const float* __restrict__ Wproj,
    const float* __restrict__ Woff, const float* __restrict__ boff)
{
    if (blockIdx.z == 0 && blockIdx.x == 0 && blockIdx.y == 0) {
        int t = threadIdx.y * 32 + threadIdx.x;
        for (int i = t; i < NQOFF_; i += 256)
            g_bias_qoff[i] = (i >= 768 && i < 768 + NOFF_) ? boff[i - 768] : 0.f;
    }

    const float* src;
    __half* dh = nullptr;
    __nv_bfloat16 *dhi = nullptr, *dlo = nullptr;
    int N, dstRows;
    switch (blockIdx.z) {
        case 0: src = Wq;    dhi = g_wqoffT_hi; dlo = g_wqoffT_lo; N = C_; dstRows = C_; break;
        case 1: src = Wk;    dh = g_wkvT;                 N = C_;   dstRows = C_;  break;
        case 2: src = Wv;    dh = g_wkvT + (long)C_ * C_; N = C_;   dstRows = C_;  break;
        case 3: src = Wproj; dh = g_wprojT_h;             N = C_;   dstRows = C_;  break;
        default: src = Woff; dhi = g_wqoffT_hi + (long)768 * C_;
                             dlo = g_wqoffT_lo + (long)768 * C_;   N = NOFF_; dstRows = 256; break;
    }
    int n0 = blockIdx.x * 32, k0 = blockIdx.y * 32;
    if (n0 >= dstRows) return;

    __shared__ float tile[32][33];
    int tx = threadIdx.x, ty = threadIdx.y;
#pragma unroll
    for (int j = 0; j < 4; j++) {
        int k = k0 + ty + j * 8, n = n0 + tx;
        tile[ty + j * 8][tx] = (n < N) ? src[(long)k * N + n] : 0.f;
    }
    __syncthreads();
#pragma unroll
    for (int j = 0; j < 4; j++) {
        int n = n0 + ty + j * 8, k = k0 + tx;
        if (n < dstRows) {
            float v = tile[tx][ty + j * 8];
            if (dh) {
                dh[(long)n * C_ + k] = __float2half_rn(v);
            } else {
                __nv_bfloat16 hi, lo;
                split_bf(v, hi, lo);
                dhi[(long)n * C_ + k] = hi;
                dlo[(long)n * C_ + k] = lo;
            }
        }
    }
}

// ---------------- GEMM bodies: 256 threads, 2 CTAs/SM -----------------------------
#define FTILE 16384
#define FSTAGE (2 * FTILE)
#define MSMEM  (3 * FSTAGE)   // 98304

// KV: C(half) = Ah @ Bh^T, 3-stage pipeline
__device__ __forceinline__ void gemm_fp16_body256(
    const __half* __restrict__ Ah, long lda,
    const __half* __restrict__ Bh,
    __half* __restrict__ C, int ldc, int K,
    int row0, int col0, char* smem)
{
    uint32_t sb = smem_to_u32(smem);
    int tid = threadIdx.x;
    int wid = tid >> 5, lane = tid & 31;
    int warp_m = wid & 3;
    int warp_n = wid >> 2;
    const int NKITER = K / 64;

    int rr[4], cc[4], doff[4];
#pragma unroll
    for (int j = 0; j < 4; j++) {
        int u = tid + j * 256;
        int r = u >> 3, cu = u & 7;
        rr[j] = r; cc[j] = cu;
        doff[j] = ((r << 3) + (cu ^ (r & 7))) << 4;
    }

    const __half* gp[2] = {Ah, Bh};
    long  st[2] = {lda, (long)K};
    int   rb[2] = {row0, col0};

#pragma unroll
    for (int s = 0; s < 2; s++) {
        uint32_t sstage = sb + s * FSTAGE;
        int k0 = s * 64;
#pragma unroll
        for (int a = 0; a < 2; a++) {
            uint32_t sdst = sstage + a * FTILE;
            const __half* g = gp[a];
#pragma unroll
            for (int j = 0; j < 4; j++)
                cp16(sdst + doff[j],
                     g + (long)(rb[a] + rr[j]) * st[a] + k0 + cc[j] * 8);
        }
        CP_COMMIT();
    }

    float acc[2][8][4];
#pragma unroll
    for (int mf = 0; mf < 2; mf++)
#pragma unroll
        for (int nf = 0; nf < 8; nf++)
#pragma unroll
            for (int e = 0; e < 4; e++) acc[mf][nf][e] = 0.f;

    int a_r = warp_m * 32 + (lane & 7) + ((lane & 8) ? 8 : 0);
    int a_usel = (lane & 16) ? 1 : 0;
    int b_rbase = warp_n * 64 + (lane & 7) + ((lane & 16) ? 8 : 0);
    int b_usel = (lane & 8) ? 1 : 0;

    int bufc = 0, bufn = 2;
    for (int kc = 0; kc < NKITER; kc++) {
        if (kc + 2 < NKITER) {
            uint32_t sstage = sb + bufn * FSTAGE;
            int k0 = (kc + 2) * 64;
#pragma unroll
            for (int a = 0; a < 2; a++) {
                uint32_t sdst = sstage + a * FTILE;
                const __half* g = gp[a];
#pragma unroll
                for (int j = 0; j < 4; j++)
                    cp16(sdst + doff[j],
                         g + (long)(rb[a] + rr[j]) * st[a] + k0 + cc[j] * 8);
            }
            CP_COMMIT();
            CP_WAIT2();
        } else if (kc + 1 < NKITER) {
            CP_WAIT1();
        } else {
            CP_WAIT0();
        }
        __syncthreads();

        uint32_t s = sb + bufc * FSTAGE;
        uint32_t sA = s, sB = s + FTILE;

#pragma unroll
        for (int ks = 0; ks < 4; ks++) {
            uint32_t af[2][4];
#pragma unroll
            for (int mf = 0; mf < 2; mf++) {
                int r = a_r + mf * 16;
                int u = ks * 2 + a_usel;
                uint32_t off = (uint32_t)(((r << 3) + (u ^ (r & 7))) << 4);
                ldm4(af[mf], sA + off);
            }
#pragma unroll
            for (int np = 0; np < 4; np++) {
                uint32_t bf[4];
                int r = b_rbase + np * 16;
                int u = ks * 2 + b_usel;
                uint32_t off = (uint32_t)(((r << 3) + (u ^ (r & 7))) << 4);
                ldm4(bf, sB + off);
#pragma unroll
                for (int mf = 0; mf < 2; mf++)
#pragma unroll
                    for (int jj = 0; jj < 2; jj++)
                        mma_fp16(acc[mf][np * 2 + jj], af[mf],
                                 bf[jj * 2], bf[jj * 2 + 1]);
            }
        }
        __syncthreads();
        bufc = (bufc == 2) ? 0 : bufc + 1;
        bufn = (bufn == 2) ? 0 : bufn + 1;
    }

#pragma unroll
    for (int mf = 0; mf < 2; mf++) {
        int m = row0 + warp_m * 32 + mf * 16 + (lane >> 2);
#pragma unroll
        for (int nf = 0; nf < 8; nf++) {
            int n = col0 + warp_n * 64 + nf * 8 + (lane & 3) * 2;
            __half2 v0 = __floats2half2_rn(acc[mf][nf][0], acc[mf][nf][1]);
            __half2 v1 = __floats2half2_rn(acc[mf][nf][2], acc[mf][nf][3]);
            *(__half2*)(C + (long)m * ldc + n)       = v0;
            *(__half2*)(C + (long)(m + 8) * ldc + n) = v1;
        }
    }
}

// fp16 2-term: C(float) = (Ahi+Alo) @ Bh^T + bias  (projection)
#define PSTAGE (3 * FTILE)
#define PSMEM  (2 * PSTAGE)   // 98304
__device__ __forceinline__ void gemm_fp16x2_body256(
    const __half* __restrict__ Ahi,
    const __half* __restrict__ Alo, long lda,
    const __half* __restrict__ Bh,
    const float* __restrict__ bias,
    float* __restrict__ C, int ldc, int K,
    int row0, int col0, char* smem)
{
    uint32_t sb = smem_to_u32(smem);
    int tid = threadIdx.x;
    int wid = tid >> 5, lane = tid & 31;
    int warp_m = wid & 3;
    int warp_n = wid >> 2;
    const int NKITER = K / 64;

    int rr[4], cc[4], doff[4];
#pragma unroll
    for (int j = 0; j < 4; j++) {
        int u = tid + j * 256;
        int r = u >> 3, cu = u & 7;
        rr[j] = r; cc[j] = cu;
        doff[j] = ((r << 3) + (cu ^ (r & 7))) << 4;
    }

    const __half* gp[3] = {Ahi, Alo, Bh};
    long  st[3] = {lda, lda, (long)K};
    int   rb[3] = {row0, row0, col0};

#pragma unroll
    for (int a = 0; a < 3; a++) {
        uint32_t sdst = sb + a * FTILE;
        const __half* g = gp[a];
#pragma unroll
        for (int j = 0; j < 4; j++)
            cp16(sdst + doff[j], g + (long)(rb[a] + rr[j]) * st[a] + cc[j] * 8);
    }
    CP_COMMIT();

    float acc[2][8][4];
#pragma unroll
    for (int mf = 0; mf < 2; mf++)
#pragma unroll
        for (int nf = 0; nf < 8; nf++)
#pragma unroll
            for (int e = 0; e < 4; e++) acc[mf][nf][e] = 0.f;

    int a_r = warp_m * 32 + (lane & 7) + ((lane & 8) ? 8 : 0);
    int a_usel = (lane & 16) ? 1 : 0;
    int b_rbase = warp_n * 64 + (lane & 7) + ((lane & 16) ? 8 : 0);
    int b_usel = (lane & 8) ? 1 : 0;

    for (int kc = 0; kc < NKITER; kc++) {
        if (kc + 1 < NKITER) {
            uint32_t sstage = sb + ((kc + 1) & 1) * PSTAGE;
            int k0 = (kc + 1) * 64;
#pragma unroll
            for (int a = 0; a < 3; a++) {
                uint32_t sdst = sstage + a * FTILE;
                const __half* g = gp[a];
#pragma unroll
                for (int j = 0; j < 4; j++)
                    cp16(sdst + doff[j],
                         g + (long)(rb[a] + rr[j]) * st[a] + k0 + cc[j] * 8);
            }
            CP_COMMIT();
            CP_WAIT1();
        } else {
            CP_WAIT0();
        }
        __syncthreads();

        uint32_t s = sb + (kc & 1) * PSTAGE;
        uint32_t sAhi = s, sAlo = s + FTILE, sB = s + 2 * FTILE;

#pragma unroll
        for (int ks = 0; ks < 4; ks++) {
            uint32_t ah[2][4], al[2][4];
#pragma unroll
            for (int mf = 0; mf < 2; mf++) {
                int r = a_r + mf * 16;
                int u = ks * 2 + a_usel;
                uint32_t off = (uint32_t)(((r << 3) + (u ^ (r & 7))) << 4);
                ldm4(ah[mf], sAhi + off);
                ldm4(al[mf], sAlo + off);
            }
#pragma unroll
            for (int np = 0; np < 4; np++) {
                uint32_t bf[4];
                int r = b_rbase + np * 16;
                int u = ks * 2 + b_usel;
                uint32_t off = (uint32_t)(((r << 3) + (u ^ (r & 7))) << 4);
                ldm4(bf, sB + off);
#pragma unroll
                for (int mf = 0; mf < 2; mf++)
#pragma unroll
                    for (int jj = 0; jj < 2; jj++) {
                        mma_fp16(acc[mf][np * 2 + jj], ah[mf],
                                 bf[jj * 2], bf[jj * 2 + 1]);
                        mma_fp16(acc[mf][np * 2 + jj], al[mf],
                                 bf[jj * 2], bf[jj * 2 + 1]);
                    }
            }
        }
        __syncthreads();
    }

#pragma unroll
    for (int mf = 0; mf < 2; mf++) {
        int m = row0 + warp_m * 32 + mf * 16 + (lane >> 2);
#pragma unroll
        for (int nf = 0; nf < 8; nf++) {
            int n = col0 + warp_n * 64 + nf * 8 + (lane & 3) * 2;
            float2 v0, v1;
            v0.x = acc[mf][nf][0]; v0.y = acc[mf][nf][1];
            v1.x = acc[mf][nf][2]; v1.y = acc[mf][nf][3];
            float bx = bias[n], by = bias[n + 1];
            v0.x += bx; v0.y += by;
            v1.x += bx; v1.y += by;
            *(float2*)(C + (long)m * ldc + n)       = v0;
            *(float2*)(C + (long)(m + 8) * ldc + n) = v1;
        }
    }
}

#define QTILE 16384
__device__ __forceinline__ void gemm_bf16x3_body256(
    const __nv_bfloat16* __restrict__ Ahi,
    const __nv_bfloat16* __restrict__ Alo, long lda,
    const __nv_bfloat16* __restrict__ Bhi,
    const __nv_bfloat16* __restrict__ Blo,
    const float* __restrict__ bias,
    float* __restrict__ C, int ldc, int Nstore, int K,
    int row0, int col0, char* smem)
{
    uint32_t sb = smem_to_u32(smem);
    int tid = threadIdx.x;
    int wid = tid >> 5, lane = tid & 31;
    int warp_m = wid & 3;
    int warp_n = wid >> 2;
    const int NKITER = K / 64;

    int rr[4], cc[4], doff[4];
#pragma unroll
    for (int j = 0; j < 4; j++) {
        int u = tid + j * 256;
        int r = u >> 3, cu = u & 7;
        rr[j] = r; cc[j] = cu;
        doff[j] = ((r << 3) + (cu ^ (r & 7))) << 4;
    }

    const __nv_bfloat16* gp[4] = {Ahi, Alo, Bhi, Blo};
    long  st[4] = {lda, lda, (long)K, (long)K};
    int   rb[4] = {row0, row0, col0, col0};

    float acc[2][8][4];
#pragma unroll
    for (int mf = 0; mf < 2; mf++)
#pragma unroll
        for (int nf = 0; nf < 8; nf++)
#pragma unroll
            for (int e = 0; e < 4; e++) acc[mf][nf][e] = 0.f;

    int a_r = warp_m * 32 + (lane & 7) + ((lane & 8) ? 8 : 0);
    int a_usel = (lane & 16) ? 1 : 0;
    int b_rbase = warp_n * 64 + (lane & 7) + ((lane & 16) ? 8 : 0);
    int b_usel = (lane & 8) ? 1 : 0;

    for (int kc = 0; kc < NKITER; kc++) {
        int k0 = kc * 64;
#pragma unroll
        for (int a = 0; a < 4; a++) {
            uint32_t sdst = sb + a * QTILE;
            const __nv_bfloat16* g = gp[a];
#pragma unroll
            for (int j = 0; j < 4; j++)
                cp16(sdst + doff[j],
                     g + (long)(rb[a] + rr[j]) * st[a] + k0 + cc[j] * 8);
        }
        CP_COMMIT();
        CP_WAIT0();
        __syncthreads();

        uint32_t sAhi = sb, sAlo = sb + QTILE;
        uint32_t sBhi = sb + 2 * QTILE, sBlo = sb + 3 * QTILE;

#pragma unroll
        for (int ks = 0; ks < 4; ks++) {
            uint32_t ah[2][4], al[2][4];
#pragma unroll
            for (int mf = 0; mf < 2; mf++) {
                int r = a_r + mf * 16;
                int u = ks * 2 + a_usel;
                uint32_t off = (uint32_t)(((r << 3) + (u ^ (r & 7))) << 4);
                ldm4(ah[mf], sAhi + off);
                ldm4(al[mf], sAlo + off);
            }
#pragma unroll
            for (int np = 0; np < 4; np++) {
                uint32_t bh[4], bl[4];
                int r = b_rbase + np * 16;
                int u = ks * 2 + b_usel;
                uint32_t off = (uint32_t)(((r << 3) + (u ^ (r & 7))) << 4);
                ldm4(bh, sBhi + off);
                ldm4(bl, sBlo + off);
#pragma unroll
                for (int mf = 0; mf < 2; mf++)
#pragma unroll
                    for (int jj = 0; jj < 2; jj++) {
                        float* a4 = acc[mf][np * 2 + jj];
                        mma_bf16(a4, ah[mf], bh[jj * 2], bh[jj * 2 + 1]);
                        mma_bf16(a4, ah[mf], bl[jj * 2], bl[jj * 2 + 1]);
                        mma_bf16(a4, al[mf], bh[jj * 2], bh[jj * 2 + 1]);
                    }
            }
        }
        __syncthreads();
    }

#pragma unroll
    for (int mf = 0; mf < 2; mf++) {
        int m = row0 + warp_m * 32 + mf * 16 + (lane >> 2);
#pragma unroll
        for (int nf = 0; nf < 8; nf++) {
            int n = col0 + warp_n * 64 + nf * 8 + (lane & 3) * 2;
            if (n < Nstore) {
                float2 v0, v1;
                v0.x = acc[mf][nf][0]; v0.y = acc[mf][nf][1];
                v1.x = acc[mf][nf][2]; v1.y = acc[mf][nf][3];
                if (bias) {
                    float bx = bias[n], by = bias[n + 1];
                    v0.x += bx; v0.y += by;
                    v1.x += bx; v1.y += by;
                }
                *(float2*)(C + (long)m * ldc + n)       = v0;
                *(float2*)(C + (long)(m + 8) * ldc + n) = v1;
            }
        }
    }
}

#define QO_BLOCKS 144
__global__ __launch_bounds__(256, 2)
void gemm_merged_kernel()
{
    extern __shared__ char smem[];
    int bid = blockIdx.x;
    if (bid < QO_BLOCKS) {
        int bx = bid % 8, by = bid / 8;
        gemm_bf16x3_body256(g_qbf_hi, g_qbf_lo, C_,
                            g_wqoffT_hi, g_wqoffT_lo, g_bias_qoff,
                            g_qoff, NQOFF_, 768 + NOFF_, C_,
                            by * 128, bx * 128, smem);
    } else {
        int b2 = bid - QO_BLOCKS;
        int bx = b2 % 12, by = b2 / 12;
        gemm_fp16_body256(g_xh, C_, g_wkvT,
                          g_kv, CKV_, C_, by * 128, bx * 128, smem);
    }
}

__global__ __launch_bounds__(256, 2)
void gemm_proj_kernel(const float* __restrict__ bias, float* __restrict__ C)
{
    extern __shared__ char smem[];
    gemm_fp16x2_body256(g_pahi, g_palo, C_, g_wprojT_h, bias,
                        C, C_, C_, blockIdx.y * 128, blockIdx.x * 128, smem);
}

// ---------------- deformable attention core ---------------------------------------
// fp16 KV + HFMA2 bilinear; fp32 packed dot/softmax.
// Softmax WITHOUT max-subtraction (logits provably bounded: |l| <~ 10 << 88),
// mathematically identical result, ~15 fewer ops per point per t.
__global__ __launch_bounds__(384, 2) void attn_kernel(
    const float* __restrict__ mask,
    const float* __restrict__ suppress_p)
{
    int bn = blockIdx.x;
    int b  = bn / N_;
    int n  = bn % N_;
    int h    = threadIdx.x >> 5;
    int lane = threadIdx.x & 31;
    int part = lane >> 4;
    int ch   = (lane & 15) * 4;

    float suppress = *suppress_p;
    float mk  = mask[bn];
    float sw  = 1.f - suppress * mk;
    float moff = suppress * mk * 0.1f;

    float refx = (float)(n % HP_) * (2.f / 23.f) - 1.f;
    float refy = (float)(n / HP_) * (2.f / 23.f) - 1.f;

    const float* rowbase = g_qoff + bn * NQOFF_;
    ulonglong2 qq = *(const ulonglong2*)(rowbase + h * DH_ + ch);

    const float* offrow = rowbase + 768 + h * (P_ * 2);
    float offv = (lane < P_ * 2) ? offrow[lane] : 0.f;

    int base_part = h * DH_ + part * C_ + ch;
    int pixbase = b * N_;

    float s0 = 0.f, s1 = 0.f, s2 = 0.f;
    u64 o0l = 0, o0h = 0, o1l = 0, o1h = 0, o2l = 0, o2h = 0;

#pragma unroll
    for (int p = 0; p < P_; p++) {
        float ox = __shfl_sync(0xffffffffu, offv, 2 * p)     - moff;
        float oy = __shfl_sync(0xffffffffu, offv, 2 * p + 1) - moff;
        float xs = (refx + ox + 1.f) * 11.5f;
        float ys = (refy + oy + 1.f) * 11.5f;
        float x0f = floorf(xs), y0f = floorf(ys);
        int   x0 = (int)x0f,  y0 = (int)y0f;
        float wx1 = xs - x0f, wy1 = ys - y0f;
        float wx0 = 1.f - wx1, wy0 = 1.f - wy1;

        // fp16 bilinear accumulators (2 half2 per t)
        uint32_t h0x = 0, h0y = 0, h1x = 0, h1y = 0, h2x = 0, h2y = 0;
#pragma unroll
        for (int c = 0; c < 4; c++) {
            int dx = c & 1, dy = c >> 1;
            int ix = x0 + dx, iy = y0 + dy;
            float valid = (ix >= 0 && ix < HP_ && iy >= 0 && iy < HP_) ? 1.f : 0.f;
            float w = (dx ? wx1 : wx0) * (dy ? wy1 : wy0) * valid;
            __half2 wh = __float2half2_rn(w);
            uint32_t w2 = *(uint32_t*)&wh;
            int ixc = min(max(ix, 0), HP_ - 1);
            int iyc = min(max(iy, 0), HP_ - 1);
            int idx = (pixbase + iyc * HP_ + ixc) * (T_ * CKV_) + base_part;
            const __half* kvp = g_kv + idx;
            uint2 kv0 = *(const uint2*)(kvp);
            uint2 kv1 = *(const uint2*)(kvp + CKV_);
            uint2 kv2 = *(const uint2*)(kvp + 2 * CKV_);
            hfma2(h0x, w2, kv0.x); hfma2(h0y, w2, kv0.y);
            hfma2(h1x, w2, kv1.x); hfma2(h1y, w2, kv1.y);
            hfma2(h2x, w2, kv2.x); hfma2(h2y, w2, kv2.y);
        }
        // convert once per point to fp32 packed
        float2 f0a = __half22float2(*(__half2*)&h0x);
        float2 f0b = __half22float2(*(__half2*)&h0y);
        float2 f1a = __half22float2(*(__half2*)&h1x);
        float2 f1b = __half22float2(*(__half2*)&h1y);
        float2 f2a = __half22float2(*(__half2*)&h2x);
        float2 f2b = __half22float2(*(__half2*)&h2y);
        u64 a0l = pack2p(f0a.x, f0a.y), a0h = pack2p(f0b.x, f0b.y);
        u64 a1l = pack2p(f1a.x, f1a.y), a1h = pack2p(f1b.x, f1b.y);
        u64 a2l = pack2p(f2a.x, f2a.y), a2h = pack2p(f2b.x, f2b.y);

        // dots (K half supplies valid values)
        u64 t0 = mul2p(qq.x, a0l); fma2p(t0, qq.y, a0h);
        u64 t1 = mul2p(qq.x, a1l); fma2p(t1, qq.y, a1h);
        u64 t2 = mul2p(qq.x, a2l); fma2p(t2, qq.y, a2h);
        float2 g0 = unpack2p(t0), g1 = unpack2p(t1), g2 = unpack2p(t2);
        float d0 = g0.x + g0.y, d1 = g1.x + g1.y, d2 = g2.x + g2.y;
#pragma unroll
        for (int s = 8; s > 0; s >>= 1) {
            d0 += __shfl_xor_sync(0xffffffffu, d0, s);
            d1 += __shfl_xor_sync(0xffffffffu, d1, s);
            d2 += __shfl_xor_sync(0xffffffffu, d2, s);
        }
        // fetch the K-half's reduced value (lane & 15 is in the K half)
        float l0 = __shfl_sync(0xffffffffu, d0, lane & 15) * SCALE_ * sw;
        float l1 = __shfl_sync(0xffffffffu, d1, lane & 15) * SCALE_ * sw;
        float l2 = __shfl_sync(0xffffffffu, d2, lane & 15) * SCALE_ * sw;

        // softmax accumulate, no max subtraction (logits bounded)
        float e0 = __expf(l0);
        float e1 = __expf(l1);
        float e2 = __expf(l2);
        s0 += e0; s1 += e1; s2 += e2;
        u64 e0p = pack2p(e0, e0);
        u64 e1p = pack2p(e1, e1);
        u64 e2p = pack2p(e2, e2);
        fma2p(o0l, e0p, a0l); fma2p(o0h, e0p, a0h);
        fma2p(o1l, e1p, a1l); fma2p(o1h, e1p, a1h);
        fma2p(o2l, e2p, a2l); fma2p(o2h, e2p, a2h);
    }

    if (part == 1) {
        const float third = 1.0f / 3.0f;
        float i0 = third / s0, i1 = third / s1, i2 = third / s2;
        u64 i0p = pack2p(i0, i0), i1p = pack2p(i1, i1), i2p = pack2p(i2, i2);
        u64 rl = mul2p(o0l, i0p); fma2p(rl, o1l, i1p); fma2p(rl, o2l, i2p);
        u64 rh = mul2p(o0h, i0p); fma2p(rh, o1h, i1p); fma2p(rh, o2h, i2p);
        float2 flo = unpack2p(rl), fhi = unpack2p(rh);

        __half hx, lx, hy, ly, hz, lz, hw, lw;
        split_h(flo.x, hx, lx); split_h(flo.y, hy, ly);
        split_h(fhi.x, hz, lz); split_h(fhi.y, hw, lw);
        int oidx = bn * C_ + h * DH_ + ch;
        __half2 hiA = __halves2half2(hx, hy), hiB = __halves2half2(hz, hw);
        __half2 loA = __halves2half2(lx, ly), loB = __halves2half2(lz, lw);
        uint2 hpack, lpack;
        hpack.x = *(uint32_t*)&hiA; hpack.y = *(uint32_t*)&hiB;
        lpack.x = *(uint32_t*)&loA; lpack.y = *(uint32_t*)&loB;
        *(uint2*)(g_pahi + oidx) = hpack;
        *(uint2*)(g_palo + oidx) = lpack;
    }
}

// ---------------- launch ----------------------------------------------------------
extern "C" void kernel_launch(void* const* d_in, const int* in_sizes, int n_in,
                              void* d_out, int out_size)
{
    const float* x     = (const float*)d_in[0];
    const float* mask  = (const float*)d_in[1];
    const float* Wq    = (const float*)d_in[2];
    const float* Wk    = (const float*)d_in[3];
    const float* Wv    = (const float*)d_in[4];
    const float* Woff  = (const float*)d_in[5];
    const float* boff  = (const float*)d_in[6];
    const float* Wproj = (const float*)d_in[7];
    const float* bproj = (const float*)d_in[8];
    const float* suppr = (const float*)d_in[9];
    float* out = (float*)d_out;

    cudaFuncSetAttribute(gemm_merged_kernel,
                         cudaFuncAttributeMaxDynamicSharedMemorySize, MSMEM);
    cudaFuncSetAttribute(gemm_proj_kernel,
                         cudaFuncAttributeMaxDynamicSharedMemorySize, PSMEM);

    conv_x_kernel<<<(MKV_ * C_ / 4 + 255) / 256, 256>>>(x);
    tpose_split_all_kernel<<<dim3(C_ / 32, C_ / 32, 5), dim3(32, 8)>>>(
        Wq, Wk, Wv, Wproj, Woff, boff);

    gemm_merged_kernel<<<QO_BLOCKS + 648, 256, MSMEM>>>();

    attn_kernel<<<BN_, 384>>>(mask, suppr);

    gemm_proj_kernel<<<dim3(C_ / 128, BN_ / 128), 256, PSMEM>>>(bproj, out);
}

// round 17
// speedup vs baseline: 1.2122x; 1.0245x over previous
#include <cuda_runtime.h>
#include <cuda_bf16.h>
#include <cuda_fp16.h>
#include <cstdint>
#include <math.h>

#define B_  4
#define N_  576
#define T_  3
#define C_  768
#define H_  12
#define P_  9
#define DH_ 64
#define HP_ 24
#define SCALE_ 0.125f
#define BN_ (B_ * N_)
#define CKV_ (2 * C_)       // 1536
#define MKV_ (BN_ * T_)     // 6912
#define NOFF_ (H_ * P_ * 2) // 216
#define NQOFF_ 1024         // 768 (q) + 256 (off padded)

typedef unsigned long long u64;

// ---------------- scratch (device globals) -----------------------------------
__device__ __half g_xh[MKV_ * C_];        // x in fp16
__device__ __half g_wkvT[CKV_ * C_];      // [n][k]; n<768: Wk, else Wv (fp16)
__device__ __nv_bfloat16 g_qbf_hi[BN_ * C_];
__device__ __nv_bfloat16 g_qbf_lo[BN_ * C_];
__device__ __nv_bfloat16 g_wqoffT_hi[NQOFF_ * C_];
__device__ __nv_bfloat16 g_wqoffT_lo[NQOFF_ * C_];
__device__ __half g_wprojT_h[C_ * C_];    // Wproj^T fp16
__device__ __half g_pahi[BN_ * C_];       // attn out fp16 hi
__device__ __half g_palo[BN_ * C_];       // attn out fp16 lo
__device__ float g_bias_qoff[NQOFF_];

__device__ __half g_kv[MKV_ * CKV_];      // fp16 KV
__device__ float g_qoff[BN_ * NQOFF_];

// ---------------- PTX helpers ---------------------------------------------------
__device__ __forceinline__ uint32_t smem_to_u32(const void* p) {
    uint32_t a;
    asm("{ .reg .u64 t; cvta.to.shared.u64 t, %1; cvt.u32.u64 %0, t; }"
        : "=r"(a) : "l"(p));
    return a;
}
__device__ __forceinline__ void cp16(uint32_t dst, const void* src) {
    asm volatile("cp.async.cg.shared.global [%0], [%1], 16;"
                 :: "r"(dst), "l"(src));
}
#define CP_COMMIT() asm volatile("cp.async.commit_group;" ::: "memory")
#define CP_WAIT0()  asm volatile("cp.async.wait_group 0;" ::: "memory")
#define CP_WAIT1()  asm volatile("cp.async.wait_group 1;" ::: "memory")

__device__ __forceinline__ void ldm4(uint32_t* r, uint32_t addr) {
    asm volatile("ldmatrix.sync.aligned.m8n8.x4.shared.b16 {%0,%1,%2,%3}, [%4];"
                 : "=r"(r[0]), "=r"(r[1]), "=r"(r[2]), "=r"(r[3]) : "r"(addr));
}
__device__ __forceinline__ void mma_bf16(float* c, const uint32_t* a,
                                         uint32_t b0, uint32_t b1) {
    asm volatile(
        "mma.sync.aligned.m16n8k16.row.col.f32.bf16.bf16.f32 "
        "{%0,%1,%2,%3}, {%4,%5,%6,%7}, {%8,%9}, {%0,%1,%2,%3};"
        : "+f"(c[0]), "+f"(c[1]), "+f"(c[2]), "+f"(c[3])
        : "r"(a[0]), "r"(a[1]), "r"(a[2]), "r"(a[3]), "r"(b0), "r"(b1));
}
__device__ __forceinline__ void mma_fp16(float* c, const uint32_t* a,
                                         uint32_t b0, uint32_t b1) {
    asm volatile(
        "mma.sync.aligned.m16n8k16.row.col.f32.f16.f16.f32 "
        "{%0,%1,%2,%3}, {%4,%5,%6,%7}, {%8,%9}, {%0,%1,%2,%3};"
        : "+f"(c[0]), "+f"(c[1]), "+f"(c[2]), "+f"(c[3])
        : "r"(a[0]), "r"(a[1]), "r"(a[2]), "r"(a[3]), "r"(b0), "r"(b1));
}

// packed math
__device__ __forceinline__ void fma2p(u64& d, u64 a, u64 b) {
    asm("fma.rn.f32x2 %0, %1, %2, %0;" : "+l"(d) : "l"(a), "l"(b));
}
__device__ __forceinline__ u64 mul2p(u64 a, u64 b) {
    u64 d; asm("mul.rn.f32x2 %0, %1, %2;" : "=l"(d) : "l"(a), "l"(b)); return d;
}
__device__ __forceinline__ u64 pack2p(float lo, float hi) {
    u64 d; asm("mov.b64 %0, {%1, %2};" : "=l"(d) : "f"(lo), "f"(hi)); return d;
}
__device__ __forceinline__ float2 unpack2p(u64 v) {
    float2 f; asm("mov.b64 {%0, %1}, %2;" : "=f"(f.x), "=f"(f.y) : "l"(v)); return f;
}
__device__ __forceinline__ void hfma2(uint32_t& d, uint32_t a, uint32_t b) {
    asm("fma.rn.f16x2 %0, %1, %2, %0;" : "+r"(d) : "r"(a), "r"(b));
}

// ---------------- fused prep kernel ------------------------------------------------
__device__ __forceinline__ void split_bf(float v, __nv_bfloat16& hi, __nv_bfloat16& lo) {
    hi = __float2bfloat16(v);
    lo = __float2bfloat16(v - __bfloat162float(hi));
}
__device__ __forceinline__ void split_h(float v, __half& hi, __half& lo) {
    hi = __float2half_rn(v);
    lo = __float2half_rn(v - __half2float(hi));
}

#define CONV_BLOCKS 5184   // (MKV_*C_/4)/256
#define TPOSE_BLOCKS (24 * 24 * 5)

__global__ void prep_kernel(
    const float* __restrict__ x,
    const float* __restrict__ Wq, const float* __restrict__ Wk,
    const float* __restrict__ Wv, const float* __restrict__ Wproj,
    const float* __restrict__ Woff, const float* __restrict__ boff)
{
    int bid = blockIdx.x;
    if (bid < CONV_BLOCKS) {
        // x -> fp16 (+ bf16 split of t=1 query rows)
        int idx = bid * 256 + threadIdx.x;
        float4 v = ((const float4*)x)[idx];
        ((__half2*)g_xh)[idx * 2]     = __floats2half2_rn(v.x, v.y);
        ((__half2*)g_xh)[idx * 2 + 1] = __floats2half2_rn(v.z, v.w);

        int token = idx / (C_ / 4);
        if (token % T_ == 1) {
            int bn = token / T_;
            int c4 = idx % (C_ / 4);
            int qidx = bn * (C_ / 4) + c4;
            __nv_bfloat16 h0, l0, h1, l1, h2, l2, h3, l3;
            split_bf(v.x, h0, l0); split_bf(v.y, h1, l1);
            split_bf(v.z, h2, l2); split_bf(v.w, h3, l3);
            ((__nv_bfloat162*)g_qbf_hi)[qidx * 2]     = __nv_bfloat162(h0, h1);
            ((__nv_bfloat162*)g_qbf_hi)[qidx * 2 + 1] = __nv_bfloat162(h2, h3);
            ((__nv_bfloat162*)g_qbf_lo)[qidx * 2]     = __nv_bfloat162(l0, l1);
            ((__nv_bfloat162*)g_qbf_lo)[qidx * 2 + 1] = __nv_bfloat162(l2, l3);
        }
        return;
    }

    // weight transpose/convert
    int r = bid - CONV_BLOCKS;
    int z   = r / 576;
    int rem = r % 576;
    int bx  = rem % 24, by = rem / 24;
    int tx = threadIdx.x & 31, ty = threadIdx.x >> 5;

    if (z == 0 && rem == 0) {
        int t = threadIdx.x;
        for (int i = t; i < NQOFF_; i += 256)
            g_bias_qoff[i] = (i >= 768 && i < 768 + NOFF_) ? boff[i - 768] : 0.f;
    }

    const float* src;
    __half* dh = nullptr;
    __nv_bfloat16 *dhi = nullptr, *dlo = nullptr;
    int N, dstRows;
    switch (z) {
        case 0: src = Wq;    dhi = g_wqoffT_hi; dlo = g_wqoffT_lo; N = C_; dstRows = C_; break;
        case 1: src = Wk;    dh = g_wkvT;                 N = C_;   dstRows = C_;  break;
        case 2: src = Wv;    dh = g_wkvT + (long)C_ * C_; N = C_;   dstRows = C_;  break;
        case 3: src = Wproj; dh = g_wprojT_h;             N = C_;   dstRows = C_;  break;
        default: src = Woff; dhi = g_wqoffT_hi + (long)768 * C_;
                             dlo = g_wqoffT_lo + (long)768 * C_;   N = NOFF_; dstRows = 256; break;
    }
    int n0 = bx * 32, k0 = by * 32;
    if (n0 >= dstRows) return;

    __shared__ float tile[32][33];
#pragma unroll
    for (int j = 0; j < 4; j++) {
        int k = k0 + ty + j * 8, n = n0 + tx;
        tile[ty + j * 8][tx] = (n < N) ? src[(long)k * N + n] : 0.f;
    }
    __syncthreads();
#pragma unroll
    for (int j = 0; j < 4; j++) {
        int n = n0 + ty + j * 8, k = k0 + tx;
        if (n < dstRows) {
            float v = tile[tx][ty + j * 8];
            if (dh) {
                dh[(long)n * C_ + k] = __float2half_rn(v);
            } else {
                __nv_bfloat16 hi, lo;
                split_bf(v, hi, lo);
                dhi[(long)n * C_ + k] = hi;
                dlo[(long)n * C_ + k] = lo;
            }
        }
    }
}

// ---------------- GEMM bodies -----------------------------------------------------
#define FTILE 16384
#define FSTAGE (2 * FTILE)
#define MSMEM  (3 * FSTAGE)   // 98304

// KV: C(half) = Ah @ Bh^T, 3-stage, SINGLE barrier per k-iter
__device__ __forceinline__ void gemm_fp16_body256(
    const __half* __restrict__ Ah, long lda,
    const __half* __restrict__ Bh,
    __half* __restrict__ C, int ldc, int K,
    int row0, int col0, char* smem)
{
    uint32_t sb = smem_to_u32(smem);
    int tid = threadIdx.x;
    int wid = tid >> 5, lane = tid & 31;
    int warp_m = wid & 3;
    int warp_n = wid >> 2;
    const int NKITER = K / 64;

    int rr[4], cc[4], doff[4];
#pragma unroll
    for (int j = 0; j < 4; j++) {
        int u = tid + j * 256;
        int r = u >> 3, cu = u & 7;
        rr[j] = r; cc[j] = cu;
        doff[j] = ((r << 3) + (cu ^ (r & 7))) << 4;
    }

    const __half* gp[2] = {Ah, Bh};
    long  st[2] = {lda, (long)K};
    int   rb[2] = {row0, col0};

#pragma unroll
    for (int s = 0; s < 2; s++) {
        uint32_t sstage = sb + s * FSTAGE;
        int k0 = s * 64;
#pragma unroll
        for (int a = 0; a < 2; a++) {
            uint32_t sdst = sstage + a * FTILE;
            const __half* g = gp[a];
#pragma unroll
            for (int j = 0; j < 4; j++)
                cp16(sdst + doff[j],
                     g + (long)(rb[a] + rr[j]) * st[a] + k0 + cc[j] * 8);
        }
        CP_COMMIT();
    }

    float acc[2][8][4];
#pragma unroll
    for (int mf = 0; mf < 2; mf++)
#pragma unroll
        for (int nf = 0; nf < 8; nf++)
#pragma unroll
            for (int e = 0; e < 4; e++) acc[mf][nf][e] = 0.f;

    int a_r = warp_m * 32 + (lane & 7) + ((lane & 8) ? 8 : 0);
    int a_usel = (lane & 16) ? 1 : 0;
    int b_rbase = warp_n * 64 + (lane & 7) + ((lane & 16) ? 8 : 0);
    int b_usel = (lane & 8) ? 1 : 0;

    for (int kc = 0; kc < NKITER; kc++) {
        if (kc + 1 < NKITER) { CP_WAIT1(); } else { CP_WAIT0(); }
        __syncthreads();
        // prefetch stage kc+2 AFTER the barrier: its buffer ((kc+2)%3 ==
        // (kc-1)%3) was read at iter kc-1, whose readers passed this barrier.
        if (kc + 2 < NKITER) {
            int bufn = (kc + 2) % 3;
            uint32_t sstage = sb + bufn * FSTAGE;
            int k0 = (kc + 2) * 64;
#pragma unroll
            for (int a = 0; a < 2; a++) {
                uint32_t sdst = sstage + a * FTILE;
                const __half* g = gp[a];
#pragma unroll
                for (int j = 0; j < 4; j++)
                    cp16(sdst + doff[j],
                         g + (long)(rb[a] + rr[j]) * st[a] + k0 + cc[j] * 8);
            }
            CP_COMMIT();
        }

        uint32_t s = sb + (kc % 3) * FSTAGE;
        uint32_t sA = s, sB = s + FTILE;

#pragma unroll
        for (int ks = 0; ks < 4; ks++) {
            uint32_t af[2][4];
#pragma unroll
            for (int mf = 0; mf < 2; mf++) {
                int r = a_r + mf * 16;
                int u = ks * 2 + a_usel;
                uint32_t off = (uint32_t)(((r << 3) + (u ^ (r & 7))) << 4);
                ldm4(af[mf], sA + off);
            }
#pragma unroll
            for (int np = 0; np < 4; np++) {
                uint32_t bf[4];
                int r = b_rbase + np * 16;
                int u = ks * 2 + b_usel;
                uint32_t off = (uint32_t)(((r << 3) + (u ^ (r & 7))) << 4);
                ldm4(bf, sB + off);
#pragma unroll
                for (int mf = 0; mf < 2; mf++)
#pragma unroll
                    for (int jj = 0; jj < 2; jj++)
                        mma_fp16(acc[mf][np * 2 + jj], af[mf],
                                 bf[jj * 2], bf[jj * 2 + 1]);
            }
        }
    }

#pragma unroll
    for (int mf = 0; mf < 2; mf++) {
        int m = row0 + warp_m * 32 + mf * 16 + (lane >> 2);
#pragma unroll
        for (int nf = 0; nf < 8; nf++) {
            int n = col0 + warp_n * 64 + nf * 8 + (lane & 3) * 2;
            __half2 v0 = __floats2half2_rn(acc[mf][nf][0], acc[mf][nf][1]);
            __half2 v1 = __floats2half2_rn(acc[mf][nf][2], acc[mf][nf][3]);
            *(__half2*)(C + (long)m * ldc + n)       = v0;
            *(__half2*)(C + (long)(m + 8) * ldc + n) = v1;
        }
    }
}

// proj: fp16 2-term, 3-stage single-sync (1 CTA/SM; 144 KB smem)
#define PSTAGE (3 * FTILE)
#define PSMEM  (3 * PSTAGE)   // 147456
__device__ __forceinline__ void gemm_fp16x2_body256(
    const __half* __restrict__ Ahi,
    const __half* __restrict__ Alo, long lda,
    const __half* __restrict__ Bh,
    const float* __restrict__ bias,
    float* __restrict__ C, int ldc, int K,
    int row0, int col0, char* smem)
{
    uint32_t sb = smem_to_u32(smem);
    int tid = threadIdx.x;
    int wid = tid >> 5, lane = tid & 31;
    int warp_m = wid & 3;
    int warp_n = wid >> 2;
    const int NKITER = K / 64;

    int rr[4], cc[4], doff[4];
#pragma unroll
    for (int j = 0; j < 4; j++) {
        int u = tid + j * 256;
        int r = u >> 3, cu = u & 7;
        rr[j] = r; cc[j] = cu;
        doff[j] = ((r << 3) + (cu ^ (r & 7))) << 4;
    }

    const __half* gp[3] = {Ahi, Alo, Bh};
    long  st[3] = {lda, lda, (long)K};
    int   rb[3] = {row0, row0, col0};

#pragma unroll
    for (int s = 0; s < 2; s++) {
        uint32_t sstage = sb + s * PSTAGE;
        int k0 = s * 64;
#pragma unroll
        for (int a = 0; a < 3; a++) {
            uint32_t sdst = sstage + a * FTILE;
            const __half* g = gp[a];
#pragma unroll
            for (int j = 0; j < 4; j++)
                cp16(sdst + doff[j],
                     g + (long)(rb[a] + rr[j]) * st[a] + k0 + cc[j] * 8);
        }
        CP_COMMIT();
    }

    float acc[2][8][4];
#pragma unroll
    for (int mf = 0; mf < 2; mf++)
#pragma unroll
        for (int nf = 0; nf < 8; nf++)
#pragma unroll
            for (int e = 0; e < 4; e++) acc[mf][nf][e] = 0.f;

    int a_r = warp_m * 32 + (lane & 7) + ((lane & 8) ? 8 : 0);
    int a_usel = (lane & 16) ? 1 : 0;
    int b_rbase = warp_n * 64 + (lane & 7) + ((lane & 16) ? 8 : 0);
    int b_usel = (lane & 8) ? 1 : 0;

    for (int kc = 0; kc < NKITER; kc++) {
        if (kc + 1 < NKITER) { CP_WAIT1(); } else { CP_WAIT0(); }
        __syncthreads();
        if (kc + 2 < NKITER) {
            int bufn = (kc + 2) % 3;
            uint32_t sstage = sb + bufn * PSTAGE;
            int k0 = (kc + 2) * 64;
#pragma unroll
            for (int a = 0; a < 3; a++) {
                uint32_t sdst = sstage + a * FTILE;
                const __half* g = gp[a];
#pragma unroll
                for (int j = 0; j < 4; j++)
                    cp16(sdst + doff[j],
                         g + (long)(rb[a] + rr[j]) * st[a] + k0 + cc[j] * 8);
            }
            CP_COMMIT();
        }

        uint32_t s = sb + (kc % 3) * PSTAGE;
        uint32_t sAhi = s, sAlo = s + FTILE, sB = s + 2 * FTILE;

#pragma unroll
        for (int ks = 0; ks < 4; ks++) {
            uint32_t ah[2][4], al[2][4];
#pragma unroll
            for (int mf = 0; mf < 2; mf++) {
                int r = a_r + mf * 16;
                int u = ks * 2 + a_usel;
                uint32_t off = (uint32_t)(((r << 3) + (u ^ (r & 7))) << 4);
                ldm4(ah[mf], sAhi + off);
                ldm4(al[mf], sAlo + off);
            }
#pragma unroll
            for (int np = 0; np < 4; np++) {
                uint32_t bf[4];
                int r = b_rbase + np * 16;
                int u = ks * 2 + b_usel;
                uint32_t off = (uint32_t)(((r << 3) + (u ^ (r & 7))) << 4);
                ldm4(bf, sB + off);
#pragma unroll
                for (int mf = 0; mf < 2; mf++)
#pragma unroll
                    for (int jj = 0; jj < 2; jj++) {
                        mma_fp16(acc[mf][np * 2 + jj], ah[mf],
                                 bf[jj * 2], bf[jj * 2 + 1]);
                        mma_fp16(acc[mf][np * 2 + jj], al[mf],
                                 bf[jj * 2], bf[jj * 2 + 1]);
                    }
            }
        }
    }

#pragma unroll
    for (int mf = 0; mf < 2; mf++) {
        int m = row0 + warp_m * 32 + mf * 16 + (lane >> 2);
#pragma unroll
        for (int nf = 0; nf < 8; nf++) {
            int n = col0 + warp_n * 64 + nf * 8 + (lane & 3) * 2;
            float2 v0, v1;
            v0.x = acc[mf][nf][0]; v0.y = acc[mf][nf][1];
            v1.x = acc[mf][nf][2]; v1.y = acc[mf][nf][3];
            float bx = bias[n], by = bias[n + 1];
            v0.x += bx; v0.y += by;
            v1.x += bx; v1.y += by;
            *(float2*)(C + (long)m * ldc + n)       = v0;
            *(float2*)(C + (long)(m + 8) * ldc + n) = v1;
        }
    }
}

#define QTILE 16384
__device__ __forceinline__ void gemm_bf16x3_body256(
    const __nv_bfloat16* __restrict__ Ahi,
    const __nv_bfloat16* __restrict__ Alo, long lda,
    const __nv_bfloat16* __restrict__ Bhi,
    const __nv_bfloat16* __restrict__ Blo,
    const float* __restrict__ bias,
    float* __restrict__ C, int ldc, int Nstore, int K,
    int row0, int col0, char* smem)
{
    uint32_t sb = smem_to_u32(smem);
    int tid = threadIdx.x;
    int wid = tid >> 5, lane = tid & 31;
    int warp_m = wid & 3;
    int warp_n = wid >> 2;
    const int NKITER = K / 64;

    int rr[4], cc[4], doff[4];
#pragma unroll
    for (int j = 0; j < 4; j++) {
        int u = tid + j * 256;
        int r = u >> 3, cu = u & 7;
        rr[j] = r; cc[j] = cu;
        doff[j] = ((r << 3) + (cu ^ (r & 7))) << 4;
    }

    const __nv_bfloat16* gp[4] = {Ahi, Alo, Bhi, Blo};
    long  st[4] = {lda, lda, (long)K, (long)K};
    int   rb[4] = {row0, row0, col0, col0};

    float acc[2][8][4];
#pragma unroll
    for (int mf = 0; mf < 2; mf++)
#pragma unroll
        for (int nf = 0; nf < 8; nf++)
#pragma unroll
            for (int e = 0; e < 4; e++) acc[mf][nf][e] = 0.f;

    int a_r = warp_m * 32 + (lane & 7) + ((lane & 8) ? 8 : 0);
    int a_usel = (lane & 16) ? 1 : 0;
    int b_rbase = warp_n * 64 + (lane & 7) + ((lane & 16) ? 8 : 0);
    int b_usel = (lane & 8) ? 1 : 0;

    for (int kc = 0; kc < NKITER; kc++) {
        int k0 = kc * 64;
#pragma unroll
        for (int a = 0; a < 4; a++) {
            uint32_t sdst = sb + a * QTILE;
            const __nv_bfloat16* g = gp[a];
#pragma unroll
            for (int j = 0; j < 4; j++)
                cp16(sdst + doff[j],
                     g + (long)(rb[a] + rr[j]) * st[a] + k0 + cc[j] * 8);
        }
        CP_COMMIT();
        CP_WAIT0();
        __syncthreads();

        uint32_t sAhi = sb, sAlo = sb + QTILE;
        uint32_t sBhi = sb + 2 * QTILE, sBlo = sb + 3 * QTILE;

#pragma unroll
        for (int ks = 0; ks < 4; ks++) {
            uint32_t ah[2][4], al[2][4];
#pragma unroll
            for (int mf = 0; mf < 2; mf++) {
                int r = a_r + mf * 16;
                int u = ks * 2 + a_usel;
                uint32_t off = (uint32_t)(((r << 3) + (u ^ (r & 7))) << 4);
                ldm4(ah[mf], sAhi + off);
                ldm4(al[mf], sAlo + off);
            }
#pragma unroll
            for (int np = 0; np < 4; np++) {
                uint32_t bh[4], bl[4];
                int r = b_rbase + np * 16;
                int u = ks * 2 + b_usel;
                uint32_t off = (uint32_t)(((r << 3) + (u ^ (r & 7))) << 4);
                ldm4(bh, sBhi + off);
                ldm4(bl, sBlo + off);
#pragma unroll
                for (int mf = 0; mf < 2; mf++)
#pragma unroll
                    for (int jj = 0; jj < 2; jj++) {
                        float* a4 = acc[mf][np * 2 + jj];
                        mma_bf16(a4, ah[mf], bh[jj * 2], bh[jj * 2 + 1]);
                        mma_bf16(a4, ah[mf], bl[jj * 2], bl[jj * 2 + 1]);
                        mma_bf16(a4, al[mf], bh[jj * 2], bh[jj * 2 + 1]);
                    }
            }
        }
        __syncthreads();
    }

#pragma unroll
    for (int mf = 0; mf < 2; mf++) {
        int m = row0 + warp_m * 32 + mf * 16 + (lane >> 2);
#pragma unroll
        for (int nf = 0; nf < 8; nf++) {
            int n = col0 + warp_n * 64 + nf * 8 + (lane & 3) * 2;
            if (n < Nstore) {
                float2 v0, v1;
                v0.x = acc[mf][nf][0]; v0.y = acc[mf][nf][1];
                v1.x = acc[mf][nf][2]; v1.y = acc[mf][nf][3];
                if (bias) {
                    float bx = bias[n], by = bias[n + 1];
                    v0.x += bx; v0.y += by;
                    v1.x += bx; v1.y += by;
                }
                *(float2*)(C + (long)m * ldc + n)       = v0;
                *(float2*)(C + (long)(m + 8) * ldc + n) = v1;
            }
        }
    }
}

#define QO_BLOCKS 144
__global__ __launch_bounds__(256, 2)
void gemm_merged_kernel()
{
    extern __shared__ char smem[];
    int bid = blockIdx.x;
    if (bid < QO_BLOCKS) {
        int bx = bid % 8, by = bid / 8;
        gemm_bf16x3_body256(g_qbf_hi, g_qbf_lo, C_,
                            g_wqoffT_hi, g_wqoffT_lo, g_bias_qoff,
                            g_qoff, NQOFF_, 768 + NOFF_, C_,
                            by * 128, bx * 128, smem);
    } else {
        int b2 = bid - QO_BLOCKS;
        int bx = b2 % 12, by = b2 / 12;
        gemm_fp16_body256(g_xh, C_, g_wkvT,
                          g_kv, CKV_, C_, by * 128, bx * 128, smem);
    }
}

__global__ __launch_bounds__(256, 1)
void gemm_proj_kernel(const float* __restrict__ bias, float* __restrict__ C)
{
    extern __shared__ char smem[];
    gemm_fp16x2_body256(g_pahi, g_palo, C_, g_wprojT_h, bias,
                        C, C_, C_, blockIdx.y * 128, blockIdx.x * 128, smem);
}

// ---------------- deformable attention core ---------------------------------------
__global__ __launch_bounds__(384, 2) void attn_kernel(
    const float* __restrict__ mask,
    const float* __restrict__ suppress_p)
{
    int bn = blockIdx.x;
    int b  = bn / N_;
    int n  = bn % N_;
    int h    = threadIdx.x >> 5;
    int lane = threadIdx.x & 31;
    int part = lane >> 4;
    int ch   = (lane & 15) * 4;

    float suppress = *suppress_p;
    float mk  = mask[bn];
    float sw  = 1.f - suppress * mk;
    float moff = suppress * mk * 0.1f;

    float refx = (float)(n % HP_) * (2.f / 23.f) - 1.f;
    float refy = (float)(n / HP_) * (2.f / 23.f) - 1.f;

    const float* rowbase = g_qoff + bn * NQOFF_;
    ulonglong2 qq = *(const ulonglong2*)(rowbase + h * DH_ + ch);
    // fold SCALE*sw into q once (exact softmax unchanged)
    {
        float qs = SCALE_ * sw;
        u64 qsp = pack2p(qs, qs);
        qq.x = mul2p(qq.x, qsp);
        qq.y = mul2p(qq.y, qsp);
    }

    const float* offrow = rowbase + 768 + h * (P_ * 2);
    float offv = (lane < P_ * 2) ? offrow[lane] : 0.f;

    int base_part = h * DH_ + part * C_ + ch;
    int pixbase = b * N_;

    float s0 = 0.f, s1 = 0.f, s2 = 0.f;
    u64 o0l = 0, o0h = 0, o1l = 0, o1h = 0, o2l = 0, o2h = 0;

#pragma unroll
    for (int p = 0; p < P_; p++) {
        float ox = __shfl_sync(0xffffffffu, offv, 2 * p)     - moff;
        float oy = __shfl_sync(0xffffffffu, offv, 2 * p + 1) - moff;
        float xs = (refx + ox + 1.f) * 11.5f;
        float ys = (refy + oy + 1.f) * 11.5f;
        float x0f = floorf(xs), y0f = floorf(ys);
        int   x0 = (int)x0f,  y0 = (int)y0f;
        float wx1 = xs - x0f, wy1 = ys - y0f;
        float wx0 = 1.f - wx1, wy0 = 1.f - wy1;

        uint32_t h0x = 0, h0y = 0, h1x = 0, h1y = 0, h2x = 0, h2y = 0;
#pragma unroll
        for (int c = 0; c < 4; c++) {
            int dx = c & 1, dy = c >> 1;
            int ix = x0 + dx, iy = y0 + dy;
            float valid = (ix >= 0 && ix < HP_ && iy >= 0 && iy < HP_) ? 1.f : 0.f;
            float w = (dx ? wx1 : wx0) * (dy ? wy1 : wy0) * valid;
            __half2 wh = __float2half2_rn(w);
            uint32_t w2 = *(uint32_t*)&wh;
            int ixc = min(max(ix, 0), HP_ - 1);
            int iyc = min(max(iy, 0), HP_ - 1);
            int idx = (pixbase + iyc * HP_ + ixc) * (T_ * CKV_) + base_part;
            const __half* kvp = g_kv + idx;
            uint2 kv0 = *(const uint2*)(kvp);
            uint2 kv1 = *(const uint2*)(kvp + CKV_);
            uint2 kv2 = *(const uint2*)(kvp + 2 * CKV_);
            hfma2(h0x, w2, kv0.x); hfma2(h0y, w2, kv0.y);
            hfma2(h1x, w2, kv1.x); hfma2(h1y, w2, kv1.y);
            hfma2(h2x, w2, kv2.x); hfma2(h2y, w2, kv2.y);
        }
        float2 f0a = __half22float2(*(__half2*)&h0x);
        float2 f0b = __half22float2(*(__half2*)&h0y);
        float2 f1a = __half22float2(*(__half2*)&h1x);
        float2 f1b = __half22float2(*(__half2*)&h1y);
        float2 f2a = __half22float2(*(__half2*)&h2x);
        float2 f2b = __half22float2(*(__half2*)&h2y);
        u64 a0l = pack2p(f0a.x, f0a.y), a0h = pack2p(f0b.x, f0b.y);
        u64 a1l = pack2p(f1a.x, f1a.y), a1h = pack2p(f1b.x, f1b.y);
        u64 a2l = pack2p(f2a.x, f2a.y), a2h = pack2p(f2b.x, f2b.y);

        u64 t0 = mul2p(qq.x, a0l); fma2p(t0, qq.y, a0h);
        u64 t1 = mul2p(qq.x, a1l); fma2p(t1, qq.y, a1h);
        u64 t2 = mul2p(qq.x, a2l); fma2p(t2, qq.y, a2h);
        float2 g0 = unpack2p(t0), g1 = unpack2p(t1), g2 = unpack2p(t2);
        float d0 = g0.x + g0.y, d1 = g1.x + g1.y, d2 = g2.x + g2.y;
#pragma unroll
        for (int s = 8; s > 0; s >>= 1) {
            d0 += __shfl_xor_sync(0xffffffffu, d0, s);
            d1 += __shfl_xor_sync(0xffffffffu, d1, s);
            d2 += __shfl_xor_sync(0xffffffffu, d2, s);
        }
        float l0 = __shfl_sync(0xffffffffu, d0, lane & 15);
        float l1 = __shfl_sync(0xffffffffu, d1, lane & 15);
        float l2 = __shfl_sync(0xffffffffu, d2, lane & 15);

        float e0 = __expf(l0);
        float e1 = __expf(l1);
        float e2 = __expf(l2);
        s0 += e0; s1 += e1; s2 += e2;
        u64 e0p = pack2p(e0, e0);
        u64 e1p = pack2p(e1, e1);
        u64 e2p = pack2p(e2, e2);
        fma2p(o0l, e0p, a0l); fma2p(o0h, e0p, a0h);
        fma2p(o1l, e1p, a1l); fma2p(o1h, e1p, a1h);
        fma2p(o2l, e2p, a2l); fma2p(o2h, e2p, a2h);
    }

    if (part == 1) {
        const float third = 1.0f / 3.0f;
        float i0 = third / s0, i1 = third / s1, i2 = third / s2;
        u64 i0p = pack2p(i0, i0), i1p = pack2p(i1, i1), i2p = pack2p(i2, i2);
        u64 rl = mul2p(o0l, i0p); fma2p(rl, o1l, i1p); fma2p(rl, o2l, i2p);
        u64 rh = mul2p(o0h, i0p); fma2p(rh, o1h, i1p); fma2p(rh, o2h, i2p);
        float2 flo = unpack2p(rl), fhi = unpack2p(rh);

        __half hx, lx, hy, ly, hz, lz, hw, lw;
        split_h(flo.x, hx, lx); split_h(flo.y, hy, ly);
        split_h(fhi.x, hz, lz); split_h(fhi.y, hw, lw);
        int oidx = bn * C_ + h * DH_ + ch;
        __half2 hiA = __halves2half2(hx, hy), hiB = __halves2half2(hz, hw);
        __half2 loA = __halves2half2(lx, ly), loB = __halves2half2(lz, lw);
        uint2 hpack, lpack;
        hpack.x = *(uint32_t*)&hiA; hpack.y = *(uint32_t*)&hiB;
        lpack.x = *(uint32_t*)&loA; lpack.y = *(uint32_t*)&loB;
        *(uint2*)(g_pahi + oidx) = hpack;
        *(uint2*)(g_palo + oidx) = lpack;
    }
}

// ---------------- launch ----------------------------------------------------------
extern "C" void kernel_launch(void* const* d_in, const int* in_sizes, int n_in,
                              void* d_out, int out_size)
{
    const float* x     = (const float*)d_in[0];
    const float* mask  = (const float*)d_in[1];
    const float* Wq    = (const float*)d_in[2];
    const float* Wk    = (const float*)d_in[3];
    const float* Wv    = (const float*)d_in[4];
    const float* Woff  = (const float*)d_in[5];
    const float* boff  = (const float*)d_in[6];
    const float* Wproj = (const float*)d_in[7];
    const float* bproj = (const float*)d_in[8];
    const float* suppr = (const float*)d_in[9];
    float* out = (float*)d_out;

    cudaFuncSetAttribute(gemm_merged_kernel,
                         cudaFuncAttributeMaxDynamicSharedMemorySize, MSMEM);
    cudaFuncSetAttribute(gemm_proj_kernel,
                         cudaFuncAttributeMaxDynamicSharedMemorySize, PSMEM);

    prep_kernel<<<CONV_BLOCKS + TPOSE_BLOCKS, 256>>>(
        x, Wq, Wk, Wv, Wproj, Woff, boff);

    gemm_merged_kernel<<<QO_BLOCKS + 648, 256, MSMEM>>>();

    attn_kernel<<<BN_, 384>>>(mask, suppr);

    gemm_proj_kernel<<<dim3(C_ / 128, BN_ / 128), 256, PSMEM>>>(bproj, out);
}